// round 1
// baseline (speedup 1.0000x reference)
#include <cuda_runtime.h>
#include <cstdint>
#include <cstddef>

// Problem constants
constexpr int kB  = 2;
constexpr int kS  = 2048;
constexpr int kH  = 2048;
constexpr int kNH = 16;
constexpr int kHD = 128;
constexpr int kM  = kB * kS;   // 4096 rows of hidden_states

// GEMM tiling
constexpr int TBM = 128;
constexpr int TBN = 128;
constexpr int TBK = 16;

// Scratch (device globals — no runtime allocation allowed)
__device__ float g_q [kB * kNH * kS * kHD];          // [b,h,s,d]  32 MB
__device__ float g_k [kB * kNH * kS * kHD];
__device__ float g_v [kB * kNH * kS * kHD];
__device__ float g_p [(size_t)kB * kNH * kS * kS];   // scores/probs 537 MB
__device__ float g_ao[(size_t)kM * kH];              // attn out, [b,s, h*HD+d]

// ---------------------------------------------------------------------------
// Unified tiled GEMM. All operands fp32.
//   MODE 0: C = A[M,K] @ W[N,K]^T, scatter into [b,h,s,d] (QKV projection)
//   MODE 1: per-head scores: A=Q[b,h] [S,HD], B=K[b,h] [S,HD], contract HD,
//           C[q,k] = scale * (q·k); blocks strictly above diagonal skipped.
//   MODE 2: per-head PV: A=P[b,h] [S,S], B=V[b,h] [S,HD] (direct layout),
//           K-loop truncated at the causal boundary; scatter to g_ao.
//   MODE 3: C = A[M,K] @ W[N,K]^T, plain row-major store (output projection)
// ---------------------------------------------------------------------------
template <int MODE>
__global__ void __launch_bounds__(256)
gemm_k(const float* __restrict__ A, const float* __restrict__ Bm,
       float* __restrict__ C, int lda, int ldb, int Kd)
{
    __shared__ __align__(16) float As[TBK][TBM + 4];
    __shared__ __align__(16) float Bs[TBK][TBN + 4];

    const int bx = blockIdx.x, by = blockIdx.y, bz = blockIdx.z;
    const int m0 = by * TBM;
    const int n0 = bx * TBN;

    if (MODE == 1) {
        if (n0 > m0) return;  // fully-masked causal block: skip (softmax zero-fills)
        A  += (size_t)bz * kS * kHD;
        Bm += (size_t)bz * kS * kHD;
        C  += (size_t)bz * kS * kS;
    }
    if (MODE == 2) {
        A  += (size_t)bz * kS * kS;
        Bm += (size_t)bz * kS * kHD;
    }

    const int kend = (MODE == 2) ? (m0 + TBM) : Kd;  // causal K truncation for PV

    const int tid = threadIdx.x;
    const int tx  = tid & 15;
    const int ty  = tid >> 4;
    const int lr  = tid >> 2;          // 0..63
    const int lc  = (tid & 3) << 2;    // 0,4,8,12

    float acc[8][8] = {};

    for (int k0 = 0; k0 < kend; k0 += TBK) {
        // --- load A tile, transposed into As[k][m] ---
        #pragma unroll
        for (int r = 0; r < 2; ++r) {
            const int row = lr + r * 64;
            const float4 av = *reinterpret_cast<const float4*>(
                A + (size_t)(m0 + row) * lda + k0 + lc);
            As[lc + 0][row] = av.x;
            As[lc + 1][row] = av.y;
            As[lc + 2][row] = av.z;
            As[lc + 3][row] = av.w;
        }
        // --- load B tile ---
        if (MODE == 2) {
            // V is [K, N] with N contiguous: direct copy into Bs[k][n]
            #pragma unroll
            for (int r = 0; r < 2; ++r) {
                const int f    = tid + r * 256;
                const int brow = f >> 5;          // 0..15
                const int bcol = (f & 31) << 2;   // 0..124
                *reinterpret_cast<float4*>(&Bs[brow][bcol]) =
                    *reinterpret_cast<const float4*>(
                        Bm + (size_t)(k0 + brow) * ldb + bcol);
            }
        } else {
            // W / K are [N, K] row-major: transposed load into Bs[k][n]
            #pragma unroll
            for (int r = 0; r < 2; ++r) {
                const int row = lr + r * 64;
                const float4 bv = *reinterpret_cast<const float4*>(
                    Bm + (size_t)(n0 + row) * ldb + k0 + lc);
                Bs[lc + 0][row] = bv.x;
                Bs[lc + 1][row] = bv.y;
                Bs[lc + 2][row] = bv.z;
                Bs[lc + 3][row] = bv.w;
            }
        }
        __syncthreads();

        #pragma unroll
        for (int kk = 0; kk < TBK; ++kk) {
            const float4 a0 = *reinterpret_cast<const float4*>(&As[kk][ty * 8]);
            const float4 a1 = *reinterpret_cast<const float4*>(&As[kk][ty * 8 + 4]);
            const float4 b0 = *reinterpret_cast<const float4*>(&Bs[kk][tx * 8]);
            const float4 b1 = *reinterpret_cast<const float4*>(&Bs[kk][tx * 8 + 4]);
            const float ra[8] = {a0.x, a0.y, a0.z, a0.w, a1.x, a1.y, a1.z, a1.w};
            const float rb[8] = {b0.x, b0.y, b0.z, b0.w, b1.x, b1.y, b1.z, b1.w};
            #pragma unroll
            for (int i = 0; i < 8; ++i)
                #pragma unroll
                for (int j = 0; j < 8; ++j)
                    acc[i][j] += ra[i] * rb[j];
        }
        __syncthreads();
    }

    // --- epilogue ---
    constexpr float scale = 0.088388347648318447f;  // 128^-0.5
    #pragma unroll
    for (int i = 0; i < 8; ++i) {
        const int row = m0 + ty * 8 + i;
        #pragma unroll
        for (int j = 0; j < 8; ++j) {
            const int col = n0 + tx * 8 + j;
            const float v = acc[i][j];
            if (MODE == 0) {
                const int b = row >> 11, s = row & (kS - 1);
                const int h = col >> 7,  d = col & (kHD - 1);
                C[((size_t)((b * kNH + h) * kS + s)) * kHD + d] = v;
            } else if (MODE == 1) {
                C[(size_t)row * kS + col] = v * scale;
            } else if (MODE == 2) {
                const int b = bz >> 4, h = bz & 15;
                C[((size_t)(b * kS + row)) * kH + h * kHD + col] = v;
            } else {
                C[(size_t)row * kH + col] = v;
            }
        }
    }
}

// ---------------------------------------------------------------------------
// Row-wise causal softmax, in place on g_p. One block per (b,h,q) row.
// Valid columns are [0, q]; columns (q, S) are written as exact 0 so the PV
// GEMM can read full 128-wide K tiles around the diagonal.
// ---------------------------------------------------------------------------
__global__ void __launch_bounds__(256) softmax_k(float* __restrict__ P)
{
    const int r  = blockIdx.x;        // 0 .. B*NH*S-1
    const int bh = r >> 11;
    const int q  = r & (kS - 1);
    float* p = P + (size_t)bh * kS * kS + (size_t)q * kS;
    const int n = q + 1;

    const int tid = threadIdx.x;
    __shared__ float red[256];

    float m = -3.402823466e+38f;
    for (int i = tid; i < n; i += 256) m = fmaxf(m, p[i]);
    red[tid] = m;
    __syncthreads();
    #pragma unroll
    for (int s = 128; s > 0; s >>= 1) {
        if (tid < s) red[tid] = fmaxf(red[tid], red[tid + s]);
        __syncthreads();
    }
    m = red[0];
    __syncthreads();

    float ev[8];
    int cnt = 0;
    float sum = 0.f;
    for (int i = tid; i < n; i += 256) {
        const float e = __expf(p[i] - m);
        ev[cnt++] = e;
        sum += e;
    }
    red[tid] = sum;
    __syncthreads();
    #pragma unroll
    for (int s = 128; s > 0; s >>= 1) {
        if (tid < s) red[tid] += red[tid + s];
        __syncthreads();
    }
    const float inv = 1.0f / red[0];

    cnt = 0;
    for (int i = tid; i < kS; i += 256) {
        p[i] = (i < n) ? ev[cnt++] * inv : 0.0f;
    }
}

// ---------------------------------------------------------------------------
extern "C" void kernel_launch(void* const* d_in, const int* in_sizes, int n_in,
                              void* d_out, int out_size)
{
    const float* hs = (const float*)d_in[0];
    // d_in[1] = attention_mask: causal 0/-1e9, applied analytically, not read
    const float* Wq = (const float*)d_in[2];
    const float* Wk = (const float*)d_in[3];
    const float* Wv = (const float*)d_in[4];
    const float* Wo = (const float*)d_in[5];
    float* out = (float*)d_out;

    float *pq, *pk, *pv, *pp, *pao;
    cudaGetSymbolAddress((void**)&pq,  g_q);
    cudaGetSymbolAddress((void**)&pk,  g_k);
    cudaGetSymbolAddress((void**)&pv,  g_v);
    cudaGetSymbolAddress((void**)&pp,  g_p);
    cudaGetSymbolAddress((void**)&pao, g_ao);

    const dim3 thr(256);

    // QKV projections: [4096,2048] @ [2048,2048]^T, scattered to [b,h,s,d]
    gemm_k<0><<<dim3(kH / TBN, kM / TBM), thr>>>(hs, Wq, pq, kH, kH, kH);
    gemm_k<0><<<dim3(kH / TBN, kM / TBM), thr>>>(hs, Wk, pk, kH, kH, kH);
    gemm_k<0><<<dim3(kH / TBN, kM / TBM), thr>>>(hs, Wv, pv, kH, kH, kH);

    // Scores: per (b,h): [2048,128] @ [2048,128]^T * scale (lower-tri blocks only)
    gemm_k<1><<<dim3(kS / TBN, kS / TBM, kB * kNH), thr>>>(pq, pk, pp, kHD, kHD, kHD);

    // Causal softmax in place
    softmax_k<<<kB * kNH * kS, 256>>>(pp);

    // PV: per (b,h): [2048,2048] @ [2048,128] with causal K truncation
    gemm_k<2><<<dim3(1, kS / TBM, kB * kNH), thr>>>(pp, pv, pao, kS, kHD, kS);

    // Output projection: [4096,2048] @ [2048,2048]^T
    gemm_k<3><<<dim3(kH / TBN, kM / TBM), thr>>>(pao, Wo, out, kH, kH, kH);
}

// round 3
// speedup vs baseline: 2.0806x; 2.0806x over previous
#include <cuda_runtime.h>
#include <cuda_bf16.h>
#include <cstdint>
#include <cstddef>

constexpr int kB  = 2;
constexpr int kS  = 2048;
constexpr int kH  = 2048;
constexpr int kNH = 16;
constexpr int kHD = 128;
constexpr int kM  = kB * kS;   // 4096

constexpr int TM = 128;
constexpr int TN = 128;
constexpr int KC = 32;         // K floats per chunk

constexpr int RSB      = 80;            // smem row stride bytes (40 bf16, 16B aligned)
constexpr int TILE_BY  = 128 * RSB;     // 10240 B per bf16 tile
constexpr int SMEM_DYN = 8 * TILE_BY;   // 2 buffers x (Ab,As,Bb,Bs) = 81920 B
// epilogue staging (128 x 132 fp32 = 67584 B) aliases the tile space

// ---- scratch (device globals) ----
__device__ float g_q [(size_t)kB * kNH * kS * kHD];   // [b,h,s,d]
__device__ float g_k [(size_t)kB * kNH * kS * kHD];   // [b,h,s,d]
__device__ float g_vT[(size_t)kB * kNH * kHD * kS];   // [b,h,d,s] (transposed)
__device__ float g_p [(size_t)kB * kNH * kS * kS];    // scores/probs
__device__ float g_ao[(size_t)kM * kH];               // attn out [b*s, h*HD+d]

// ---------------------------------------------------------------------------
__device__ __forceinline__ uint32_t smem_u32(const void* p) {
    uint32_t a;
    asm("{ .reg .u64 t; cvta.to.shared.u64 t, %1; cvt.u32.u64 %0, t; }"
        : "=r"(a) : "l"(p));
    return a;
}
__device__ __forceinline__ void ldsm4(uint32_t* d, uint32_t addr) {
    asm volatile("ldmatrix.sync.aligned.m8n8.x4.shared.b16 {%0,%1,%2,%3}, [%4];"
                 : "=r"(d[0]), "=r"(d[1]), "=r"(d[2]), "=r"(d[3]) : "r"(addr));
}
__device__ __forceinline__ void mma_bf16(float* c, const uint32_t* a,
                                         const uint32_t* b) {
    asm volatile(
        "mma.sync.aligned.m16n8k16.row.col.f32.bf16.bf16.f32 "
        "{%0,%1,%2,%3}, {%4,%5,%6,%7}, {%8,%9}, {%0,%1,%2,%3};"
        : "+f"(c[0]), "+f"(c[1]), "+f"(c[2]), "+f"(c[3])
        : "r"(a[0]), "r"(a[1]), "r"(a[2]), "r"(a[3]), "r"(b[0]), "r"(b[1]));
}
__device__ __forceinline__ uint32_t pk2(__nv_bfloat16 a, __nv_bfloat16 b) {
    __nv_bfloat162 t(a, b);
    return *reinterpret_cast<uint32_t*>(&t);
}

// Convert float4 -> (big, small) bf16 quads, store 8B each.
__device__ __forceinline__ void cvt_sts(char* dsm, int off_b, int off_s,
                                        int r, int cflt, float4 x) {
    const __nv_bfloat16 b0 = __float2bfloat16_rn(x.x);
    const __nv_bfloat16 b1 = __float2bfloat16_rn(x.y);
    const __nv_bfloat16 b2 = __float2bfloat16_rn(x.z);
    const __nv_bfloat16 b3 = __float2bfloat16_rn(x.w);
    const __nv_bfloat16 s0 = __float2bfloat16_rn(x.x - __bfloat162float(b0));
    const __nv_bfloat16 s1 = __float2bfloat16_rn(x.y - __bfloat162float(b1));
    const __nv_bfloat16 s2 = __float2bfloat16_rn(x.z - __bfloat162float(b2));
    const __nv_bfloat16 s3 = __float2bfloat16_rn(x.w - __bfloat162float(b3));
    uint2 vb = {pk2(b0, b1), pk2(b2, b3)};
    uint2 vs = {pk2(s0, s1), pk2(s2, s3)};
    const int byo = r * RSB + cflt * 2;
    *reinterpret_cast<uint2*>(dsm + off_b + byo) = vb;
    *reinterpret_cast<uint2*>(dsm + off_s + byo) = vs;
}

// ---------------------------------------------------------------------------
//  MODE 0: proj -> scatter [b,h,s,d]   (Q, K)
//  MODE 4: proj -> scatter [b,h,d,s]   (V transposed)
//  MODE 1: scores per head (lower-tri blocks only), * HD^-0.5
//  MODE 2: PV per head (B = g_vT K-major), causal K truncation
//  MODE 3: plain row-major store       (O proj)
// A is MxK K-major, B is NxK K-major in all modes.
// ---------------------------------------------------------------------------
template <int MODE>
__global__ void __launch_bounds__(256, 1)
mm_k(const float* __restrict__ A, const float* __restrict__ Bm,
     float* __restrict__ C, int lda, int ldb, int Kd)
{
    extern __shared__ char dsm[];
    const int bx = blockIdx.x, by = blockIdx.y, bz = blockIdx.z;
    const int m0 = by * TM;
    const int n0 = bx * TN;

    if (MODE == 1 && n0 > m0) return;   // fully-masked causal block

    if (MODE == 1) {
        A  += (size_t)bz * kS * kHD;
        Bm += (size_t)bz * kS * kHD;
        C  += (size_t)bz * kS * kS;
    }
    if (MODE == 2) {
        A  += (size_t)bz * kS * kS;
        Bm += (size_t)bz * kHD * kS;
    }
    const int kend = (MODE == 2) ? (m0 + TM) : Kd;
    const int NC   = kend / KC;

    const int tid  = threadIdx.x;
    const int lane = tid & 31;
    const int wid  = tid >> 5;
    const int wm   = (wid & 3) * 32;     // warp M offset
    const int wn   = (wid >> 2) * 64;    // warp N offset
    const uint32_t sb = smem_u32(dsm);

    const int lr = tid >> 1;             // load row 0..127
    const int lc = (tid & 1) * 16;       // load col (floats)

    float acc[2][8][4];
    #pragma unroll
    for (int i = 0; i < 2; ++i)
        #pragma unroll
        for (int j = 0; j < 8; ++j)
            #pragma unroll
            for (int t = 0; t < 4; ++t) acc[i][j][t] = 0.f;

    // ---- prologue: chunk 0 -> buffer 0
    {
        const float* sA = A  + (size_t)(m0 + lr) * lda + lc;
        const float* sB = Bm + (size_t)(n0 + lr) * ldb + lc;
        #pragma unroll
        for (int j = 0; j < 4; ++j) {
            cvt_sts(dsm, 0,           TILE_BY,     lr, lc + 4 * j,
                    *reinterpret_cast<const float4*>(sA + 4 * j));
            cvt_sts(dsm, 2 * TILE_BY, 3 * TILE_BY, lr, lc + 4 * j,
                    *reinterpret_cast<const float4*>(sB + 4 * j));
        }
    }
    __syncthreads();

    for (int c = 0; c < NC; ++c) {
        const int cur = c & 1;
        const bool more = (c + 1 < NC);

        float4 pre[8];
        if (more) {
            const int k1 = (c + 1) * KC;
            const float* sA = A  + (size_t)(m0 + lr) * lda + k1 + lc;
            const float* sB = Bm + (size_t)(n0 + lr) * ldb + k1 + lc;
            #pragma unroll
            for (int j = 0; j < 4; ++j) {
                pre[j]     = *reinterpret_cast<const float4*>(sA + 4 * j);
                pre[4 + j] = *reinterpret_cast<const float4*>(sB + 4 * j);
            }
        }

        // ---- compute chunk `cur`
        {
            const uint32_t ab = sb + cur * 4 * TILE_BY;
            const uint32_t as = ab + TILE_BY;
            const uint32_t bb = ab + 2 * TILE_BY;
            const uint32_t bsm = ab + 3 * TILE_BY;
            #pragma unroll
            for (int ks = 0; ks < KC; ks += 16) {
                uint32_t afb[2][4], afs[2][4], bfb[8][2], bfs[8][2];
                #pragma unroll
                for (int i = 0; i < 2; ++i) {
                    const int row = wm + 16 * i + (lane & 15);
                    const int col = ks + ((lane >> 4) << 3);
                    const uint32_t off = row * RSB + col * 2;
                    ldsm4(afb[i], ab + off);
                    ldsm4(afs[i], as + off);
                }
                #pragma unroll
                for (int jj = 0; jj < 4; ++jj) {
                    const int row = wn + 16 * jj + (lane & 7) + ((lane >> 4) << 3);
                    const int col = ks + (((lane >> 3) & 1) << 3);
                    const uint32_t off = row * RSB + col * 2;
                    ldsm4(&bfb[2 * jj][0], bb + off);
                    ldsm4(&bfs[2 * jj][0], bsm + off);
                }
                #pragma unroll
                for (int i = 0; i < 2; ++i)
                    #pragma unroll
                    for (int j = 0; j < 8; ++j) {
                        mma_bf16(acc[i][j], afb[i], bfb[j]);
                        mma_bf16(acc[i][j], afb[i], bfs[j]);
                        mma_bf16(acc[i][j], afs[i], bfb[j]);
                    }
            }
        }

        if (more) {
            const int nb = (cur ^ 1) * 4 * TILE_BY;
            #pragma unroll
            for (int j = 0; j < 4; ++j) {
                cvt_sts(dsm, nb,               nb + TILE_BY,     lr, lc + 4 * j, pre[j]);
                cvt_sts(dsm, nb + 2 * TILE_BY, nb + 3 * TILE_BY, lr, lc + 4 * j, pre[4 + j]);
            }
        }
        __syncthreads();
    }

    // ---- epilogue: accumulators -> smem staging -> coalesced gmem
    float* ep = reinterpret_cast<float*>(dsm);
    constexpr float scale = 0.088388347648318447f;  // 128^-0.5
    #pragma unroll
    for (int i = 0; i < 2; ++i)
        #pragma unroll
        for (int j = 0; j < 8; ++j) {
            const int r0 = wm + 16 * i + (lane >> 2);
            const int c0 = wn + 8 * j + 2 * (lane & 3);
            float v0 = acc[i][j][0], v1 = acc[i][j][1];
            float v2 = acc[i][j][2], v3 = acc[i][j][3];
            if (MODE == 1) { v0 *= scale; v1 *= scale; v2 *= scale; v3 *= scale; }
            ep[r0 * 132 + c0]       = v0;
            ep[r0 * 132 + c0 + 1]   = v1;
            ep[(r0 + 8) * 132 + c0]     = v2;
            ep[(r0 + 8) * 132 + c0 + 1] = v3;
        }
    __syncthreads();

    if (MODE == 4) {
        const int d    = tid >> 1;          // head-dim index (ep column)
        const int mseg = (tid & 1) * 64;    // s segment
        const int h = n0 >> 7, b = m0 >> 11;
        float* dst = C + ((size_t)((b * kNH + h) * kHD + d)) * kS +
                     (m0 & (kS - 1)) + mseg;
        #pragma unroll
        for (int j = 0; j < 16; ++j) {
            float4 v;
            v.x = ep[(mseg + 4 * j + 0) * 132 + d];
            v.y = ep[(mseg + 4 * j + 1) * 132 + d];
            v.z = ep[(mseg + 4 * j + 2) * 132 + d];
            v.w = ep[(mseg + 4 * j + 3) * 132 + d];
            *reinterpret_cast<float4*>(dst + 4 * j) = v;
        }
    } else {
        const int r   = tid >> 1;
        const int c0  = (tid & 1) * 64;
        const int row = m0 + r;
        float* dst;
        if (MODE == 0) {
            const int b = row >> 11, s = row & (kS - 1), h = n0 >> 7;
            dst = C + ((size_t)((b * kNH + h) * kS + s)) * kHD;
        } else if (MODE == 1) {
            dst = C + (size_t)row * kS + n0;
        } else if (MODE == 2) {
            const int b = bz >> 4, h = bz & 15;
            dst = C + ((size_t)(b * kS + row)) * kH + h * kHD;
        } else {
            dst = C + (size_t)row * kH + n0;
        }
        #pragma unroll
        for (int j = 0; j < 16; ++j) {
            const int cc = c0 + 4 * j;
            float4 v;
            v.x = ep[r * 132 + cc + 0];
            v.y = ep[r * 132 + cc + 1];
            v.z = ep[r * 132 + cc + 2];
            v.w = ep[r * 132 + cc + 3];
            *reinterpret_cast<float4*>(dst + cc) = v;
        }
    }
}

// ---------------------------------------------------------------------------
// Row-wise causal softmax, in place. Zero-fill to the next 128 boundary
// (PV truncates its K loop there).
// ---------------------------------------------------------------------------
__global__ void __launch_bounds__(256) softmax_k(float* __restrict__ P)
{
    const int r  = blockIdx.x;
    const int bh = r >> 11;
    const int q  = r & (kS - 1);
    float* p = P + (size_t)bh * kS * kS + (size_t)q * kS;
    const int n    = q + 1;
    const int npad = ((q >> 7) + 1) << 7;

    const int tid = threadIdx.x;
    __shared__ float red[256];

    float m = -3.402823466e+38f;
    for (int i = tid; i < n; i += 256) m = fmaxf(m, p[i]);
    red[tid] = m;
    __syncthreads();
    #pragma unroll
    for (int s = 128; s > 0; s >>= 1) {
        if (tid < s) red[tid] = fmaxf(red[tid], red[tid + s]);
        __syncthreads();
    }
    m = red[0];
    __syncthreads();

    float ev[8];
    int cnt = 0;
    float sum = 0.f;
    for (int i = tid; i < n; i += 256) {
        const float e = __expf(p[i] - m);
        ev[cnt++] = e;
        sum += e;
    }
    red[tid] = sum;
    __syncthreads();
    #pragma unroll
    for (int s = 128; s > 0; s >>= 1) {
        if (tid < s) red[tid] += red[tid + s];
        __syncthreads();
    }
    const float inv = 1.0f / red[0];

    cnt = 0;
    for (int i = tid; i < npad; i += 256)
        p[i] = (i < n) ? ev[cnt++] * inv : 0.0f;
}

// ---------------------------------------------------------------------------
extern "C" void kernel_launch(void* const* d_in, const int* in_sizes, int n_in,
                              void* d_out, int out_size)
{
    const float* hs = (const float*)d_in[0];
    // d_in[1] = attention_mask (causal; applied analytically)
    const float* Wq = (const float*)d_in[2];
    const float* Wk = (const float*)d_in[3];
    const float* Wv = (const float*)d_in[4];
    const float* Wo = (const float*)d_in[5];
    float* out = (float*)d_out;

    float *pq, *pk, *pvT, *pp, *pao;
    cudaGetSymbolAddress((void**)&pq,  g_q);
    cudaGetSymbolAddress((void**)&pk,  g_k);
    cudaGetSymbolAddress((void**)&pvT, g_vT);
    cudaGetSymbolAddress((void**)&pp,  g_p);
    cudaGetSymbolAddress((void**)&pao, g_ao);

    cudaFuncSetAttribute(mm_k<0>, cudaFuncAttributeMaxDynamicSharedMemorySize, SMEM_DYN);
    cudaFuncSetAttribute(mm_k<1>, cudaFuncAttributeMaxDynamicSharedMemorySize, SMEM_DYN);
    cudaFuncSetAttribute(mm_k<2>, cudaFuncAttributeMaxDynamicSharedMemorySize, SMEM_DYN);
    cudaFuncSetAttribute(mm_k<3>, cudaFuncAttributeMaxDynamicSharedMemorySize, SMEM_DYN);
    cudaFuncSetAttribute(mm_k<4>, cudaFuncAttributeMaxDynamicSharedMemorySize, SMEM_DYN);

    const dim3 thr(256);

    mm_k<0><<<dim3(kH / TN, kM / TM), thr, SMEM_DYN>>>(hs, Wq, pq,  kH, kH, kH);
    mm_k<0><<<dim3(kH / TN, kM / TM), thr, SMEM_DYN>>>(hs, Wk, pk,  kH, kH, kH);
    mm_k<4><<<dim3(kH / TN, kM / TM), thr, SMEM_DYN>>>(hs, Wv, pvT, kH, kH, kH);

    mm_k<1><<<dim3(kS / TN, kS / TM, kB * kNH), thr, SMEM_DYN>>>(pq, pk, pp,
                                                                 kHD, kHD, kHD);
    softmax_k<<<kB * kNH * kS, 256>>>(pp);

    mm_k<2><<<dim3(1, kS / TM, kB * kNH), thr, SMEM_DYN>>>(pp, pvT, pao,
                                                           kS, kS, kS);

    mm_k<3><<<dim3(kH / TN, kM / TM), thr, SMEM_DYN>>>(pao, Wo, out, kH, kH, kH);
}

// round 4
// speedup vs baseline: 2.7904x; 1.3412x over previous
#include <cuda_runtime.h>
#include <cuda_bf16.h>
#include <cstdint>
#include <cstddef>

using bf16 = __nv_bfloat16;

constexpr int kB  = 2;
constexpr int kS  = 2048;
constexpr int kH  = 2048;
constexpr int kNH = 16;
constexpr int kHD = 128;
constexpr int kM  = kB * kS;   // 4096

constexpr int TM = 128;
constexpr int TN = 128;
constexpr int KC = 32;                 // K elems per chunk (64B rows in smem)

constexpr int TILE   = 128 * 64;       // 8192 B per bf16 plane tile
constexpr int STAGE  = 4 * TILE;       // Ab, As, Bb, Bs
constexpr int NSTAGE = 3;
constexpr int SMEM_DYN = NSTAGE * STAGE;  // 98304 B

// ---- scratch: split bf16 planes + fp32 scores ----
__device__ bf16 g_hb [(size_t)kM * kH],  g_hs [(size_t)kM * kH];
__device__ bf16 g_wb [4][(size_t)kH * kH], g_ws [4][(size_t)kH * kH]; // q,k,v,o
__device__ bf16 g_qb [(size_t)kB * kNH * kS * kHD], g_qs [(size_t)kB * kNH * kS * kHD];
__device__ bf16 g_kb [(size_t)kB * kNH * kS * kHD], g_ks2[(size_t)kB * kNH * kS * kHD];
__device__ bf16 g_vtb[(size_t)kB * kNH * kHD * kS], g_vts[(size_t)kB * kNH * kHD * kS];
__device__ float g_p [(size_t)kB * kNH * kS * kS];
__device__ bf16 g_pb [(size_t)kB * kNH * kS * kS], g_ps [(size_t)kB * kNH * kS * kS];
__device__ bf16 g_aob[(size_t)kM * kH], g_aos[(size_t)kM * kH];

// ---------------------------------------------------------------------------
__device__ __forceinline__ uint32_t smem_u32(const void* p) {
    uint32_t a;
    asm("{ .reg .u64 t; cvta.to.shared.u64 t, %1; cvt.u32.u64 %0, t; }"
        : "=r"(a) : "l"(p));
    return a;
}
__device__ __forceinline__ void ldsm4(uint32_t* d, uint32_t addr) {
    asm volatile("ldmatrix.sync.aligned.m8n8.x4.shared.b16 {%0,%1,%2,%3}, [%4];"
                 : "=r"(d[0]), "=r"(d[1]), "=r"(d[2]), "=r"(d[3]) : "r"(addr));
}
__device__ __forceinline__ void mma_bf16(float* c, const uint32_t* a,
                                         const uint32_t* b) {
    asm volatile(
        "mma.sync.aligned.m16n8k16.row.col.f32.bf16.bf16.f32 "
        "{%0,%1,%2,%3}, {%4,%5,%6,%7}, {%8,%9}, {%0,%1,%2,%3};"
        : "+f"(c[0]), "+f"(c[1]), "+f"(c[2]), "+f"(c[3])
        : "r"(a[0]), "r"(a[1]), "r"(a[2]), "r"(a[3]), "r"(b[0]), "r"(b[1]));
}
__device__ __forceinline__ void cpa16(uint32_t dst, const void* src) {
    asm volatile("cp.async.cg.shared.global [%0], [%1], 16;"
                 :: "r"(dst), "l"(__cvta_generic_to_global(src)));
}
#define CP_COMMIT() asm volatile("cp.async.commit_group;" ::: "memory")

__device__ __forceinline__ uint32_t pk2(bf16 a, bf16 b) {
    __nv_bfloat162 t(a, b);
    return *reinterpret_cast<uint32_t*>(&t);
}
// Store 4 fp32 as (big, small) bf16 quads into two planes.
__device__ __forceinline__ void store_split4(bf16* pb_, bf16* ps_,
                                             float x, float y, float z, float w) {
    const bf16 b0 = __float2bfloat16_rn(x), b1 = __float2bfloat16_rn(y);
    const bf16 b2 = __float2bfloat16_rn(z), b3 = __float2bfloat16_rn(w);
    const bf16 s0 = __float2bfloat16_rn(x - __bfloat162float(b0));
    const bf16 s1 = __float2bfloat16_rn(y - __bfloat162float(b1));
    const bf16 s2 = __float2bfloat16_rn(z - __bfloat162float(b2));
    const bf16 s3 = __float2bfloat16_rn(w - __bfloat162float(b3));
    uint2 vb = {pk2(b0, b1), pk2(b2, b3)};
    uint2 vs = {pk2(s0, s1), pk2(s2, s3)};
    *reinterpret_cast<uint2*>(pb_) = vb;
    *reinterpret_cast<uint2*>(ps_) = vs;
}

// ---------------------------------------------------------------------------
// fp32 -> (big, small) bf16 planes, vectorized by 4.
__global__ void __launch_bounds__(256) split_k(const float4* __restrict__ src,
                                               uint2* __restrict__ db,
                                               uint2* __restrict__ ds, int n4)
{
    const int i = blockIdx.x * 256 + threadIdx.x;
    if (i >= n4) return;
    const float4 v = src[i];
    const bf16 b0 = __float2bfloat16_rn(v.x), b1 = __float2bfloat16_rn(v.y);
    const bf16 b2 = __float2bfloat16_rn(v.z), b3 = __float2bfloat16_rn(v.w);
    const bf16 s0 = __float2bfloat16_rn(v.x - __bfloat162float(b0));
    const bf16 s1 = __float2bfloat16_rn(v.y - __bfloat162float(b1));
    const bf16 s2 = __float2bfloat16_rn(v.z - __bfloat162float(b2));
    const bf16 s3 = __float2bfloat16_rn(v.w - __bfloat162float(b3));
    db[i] = {pk2(b0, b1), pk2(b2, b3)};
    ds[i] = {pk2(s0, s1), pk2(s2, s3)};
}

// ---------------------------------------------------------------------------
//  MODE 0: proj -> split planes [b,h,s,d]     (Q, K)
//  MODE 4: proj -> split planes [b,h,d,s]     (V transposed)
//  MODE 1: scores (lower-tri blocks) -> fp32 * HD^-0.5
//  MODE 2: PV (causal K truncation) -> split planes [b*s, h*HD+d]
//  MODE 3: O proj -> fp32 row-major
// A is MxK K-major, B is NxK K-major, both as (big,small) bf16 planes.
// ---------------------------------------------------------------------------
template <int MODE>
__global__ void __launch_bounds__(256, 2)
mm_k(const bf16* __restrict__ Ab, const bf16* __restrict__ As,
     const bf16* __restrict__ Bb, const bf16* __restrict__ Bs,
     float* __restrict__ Cf, bf16* __restrict__ Cb, bf16* __restrict__ Cs,
     int lda, int ldb, int Kd)
{
    extern __shared__ char dsm[];
    const int bx = blockIdx.x, by = blockIdx.y, bz = blockIdx.z;
    const int m0 = by * TM;
    const int n0 = bx * TN;

    if (MODE == 1 && n0 > m0) return;

    if (MODE == 1) {
        Ab += (size_t)bz * kS * kHD;  As += (size_t)bz * kS * kHD;
        Bb += (size_t)bz * kS * kHD;  Bs += (size_t)bz * kS * kHD;
        Cf += (size_t)bz * kS * kS;
    }
    if (MODE == 2) {
        Ab += (size_t)bz * kS * kS;   As += (size_t)bz * kS * kS;
        Bb += (size_t)bz * kHD * kS;  Bs += (size_t)bz * kHD * kS;
    }
    const int kend = (MODE == 2) ? (m0 + TM) : Kd;
    const int NC   = kend / KC;

    const int tid  = threadIdx.x;
    const int lane = tid & 31;
    const int wid  = tid >> 5;
    const int wm   = (wid & 3) * 32;
    const int wn   = (wid >> 2) * 64;
    const uint32_t sb = smem_u32(dsm);

    float acc[2][8][4];
    #pragma unroll
    for (int i = 0; i < 2; ++i)
        #pragma unroll
        for (int j = 0; j < 8; ++j)
            #pragma unroll
            for (int t = 0; t < 4; ++t) acc[i][j][t] = 0.f;

    auto load_stage = [&](int c) {
        const uint32_t base = sb + (c % NSTAGE) * STAGE;
        const int k0 = c * KC;
        #pragma unroll
        for (int it = 0; it < 2; ++it) {
            const int idx = tid + it * 256;
            const int r = idx >> 2, c16 = idx & 3;
            const uint32_t d = base + r * 64 + ((c16 ^ ((r >> 1) & 3)) << 4);
            const size_t ao = (size_t)(m0 + r) * lda + k0 + c16 * 8;
            const size_t bo = (size_t)(n0 + r) * ldb + k0 + c16 * 8;
            cpa16(d,            Ab + ao);
            cpa16(d + TILE,     As + ao);
            cpa16(d + 2 * TILE, Bb + bo);
            cpa16(d + 3 * TILE, Bs + bo);
        }
    };

    load_stage(0); CP_COMMIT();
    load_stage(1); CP_COMMIT();

    for (int c = 0; c < NC; ++c) {
        if (c + 2 <= NC) asm volatile("cp.async.wait_group 1;" ::: "memory");
        else             asm volatile("cp.async.wait_group 0;" ::: "memory");
        __syncthreads();

        const uint32_t ab = sb + (c % NSTAGE) * STAGE;
        #pragma unroll
        for (int ks = 0; ks < 2; ++ks) {
            uint32_t afb[2][4], afs[2][4];
            #pragma unroll
            for (int i = 0; i < 2; ++i) {
                const int row = wm + 16 * i + (lane & 15);
                const int c16 = 2 * ks + (lane >> 4);
                const uint32_t off = row * 64 + ((c16 ^ ((row >> 1) & 3)) << 4);
                ldsm4(afb[i], ab + off);
                ldsm4(afs[i], ab + TILE + off);
            }
            #pragma unroll
            for (int jj = 0; jj < 4; ++jj) {
                const int row = wn + 16 * jj + (lane & 7) + ((lane >> 4) << 3);
                const int c16 = 2 * ks + ((lane >> 3) & 1);
                const uint32_t off = row * 64 + ((c16 ^ ((row >> 1) & 3)) << 4);
                uint32_t bb4[4], bs4[4];
                ldsm4(bb4, ab + 2 * TILE + off);
                ldsm4(bs4, ab + 3 * TILE + off);
                #pragma unroll
                for (int i = 0; i < 2; ++i)
                    #pragma unroll
                    for (int j2 = 0; j2 < 2; ++j2) {
                        float* a_ = acc[i][2 * jj + j2];
                        mma_bf16(a_, afb[i], bb4 + 2 * j2);
                        mma_bf16(a_, afb[i], bs4 + 2 * j2);
                        mma_bf16(a_, afs[i], bb4 + 2 * j2);
                    }
            }
        }
        if (c + 2 < NC) { load_stage(c + 2); CP_COMMIT(); }
        __syncthreads();
    }

    // ---- epilogue: accumulators -> smem staging (fp32) -> gmem
    float* ep = reinterpret_cast<float*>(dsm);
    constexpr float scale = 0.088388347648318447f;  // 128^-0.5
    #pragma unroll
    for (int i = 0; i < 2; ++i)
        #pragma unroll
        for (int j = 0; j < 8; ++j) {
            const int r0 = wm + 16 * i + (lane >> 2);
            const int c0 = wn + 8 * j + 2 * (lane & 3);
            float v0 = acc[i][j][0], v1 = acc[i][j][1];
            float v2 = acc[i][j][2], v3 = acc[i][j][3];
            if (MODE == 1) { v0 *= scale; v1 *= scale; v2 *= scale; v3 *= scale; }
            ep[r0 * 132 + c0]           = v0;
            ep[r0 * 132 + c0 + 1]       = v1;
            ep[(r0 + 8) * 132 + c0]     = v2;
            ep[(r0 + 8) * 132 + c0 + 1] = v3;
        }
    __syncthreads();

    if (MODE == 4) {
        const int d    = tid >> 1;
        const int mseg = (tid & 1) * 64;
        const int h = n0 >> 7, b = m0 >> 11;
        const size_t base = ((size_t)((b * kNH + h) * kHD + d)) * kS +
                            (m0 & (kS - 1)) + mseg;
        #pragma unroll
        for (int j = 0; j < 16; ++j) {
            store_split4(Cb + base + 4 * j, Cs + base + 4 * j,
                         ep[(mseg + 4 * j + 0) * 132 + d],
                         ep[(mseg + 4 * j + 1) * 132 + d],
                         ep[(mseg + 4 * j + 2) * 132 + d],
                         ep[(mseg + 4 * j + 3) * 132 + d]);
        }
    } else {
        const int r   = tid >> 1;
        const int c0  = (tid & 1) * 64;
        const int row = m0 + r;
        size_t base;
        if (MODE == 0) {
            const int b = row >> 11, s = row & (kS - 1), h = n0 >> 7;
            base = ((size_t)((b * kNH + h) * kS + s)) * kHD + c0;
        } else if (MODE == 1) {
            base = (size_t)row * kS + n0 + c0;
        } else if (MODE == 2) {
            const int b = bz >> 4, h = bz & 15;
            base = ((size_t)(b * kS + row)) * kH + h * kHD + c0;
        } else {
            base = (size_t)row * kH + n0 + c0;
        }
        #pragma unroll
        for (int j = 0; j < 16; ++j) {
            const int cc = c0 + 4 * j;
            const float v0 = ep[r * 132 + cc + 0];
            const float v1 = ep[r * 132 + cc + 1];
            const float v2 = ep[r * 132 + cc + 2];
            const float v3 = ep[r * 132 + cc + 3];
            if (MODE == 1 || MODE == 3) {
                float4 v = {v0, v1, v2, v3};
                *reinterpret_cast<float4*>(Cf + base + 4 * j) = v;
            } else {
                store_split4(Cb + base + 4 * j, Cs + base + 4 * j, v0, v1, v2, v3);
            }
        }
    }
}

// ---------------------------------------------------------------------------
// Row-wise causal softmax: fp32 scores in, split-bf16 probabilities out.
// Zero-fills both planes up to the 128-aligned boundary.
// ---------------------------------------------------------------------------
__global__ void __launch_bounds__(256) softmax_k(const float* __restrict__ P,
                                                bf16* __restrict__ Pb,
                                                bf16* __restrict__ Ps)
{
    const int r  = blockIdx.x;
    const int bh = r >> 11;
    const int q  = r & (kS - 1);
    const size_t off = (size_t)bh * kS * kS + (size_t)q * kS;
    const float* p = P + off;
    const int n    = q + 1;
    const int npad = ((q >> 7) + 1) << 7;

    const int tid = threadIdx.x;
    __shared__ float red[256];

    float m = -3.402823466e+38f;
    for (int i = tid; i < n; i += 256) m = fmaxf(m, p[i]);
    red[tid] = m;
    __syncthreads();
    #pragma unroll
    for (int s = 128; s > 0; s >>= 1) {
        if (tid < s) red[tid] = fmaxf(red[tid], red[tid + s]);
        __syncthreads();
    }
    m = red[0];
    __syncthreads();

    float ev[8];
    int cnt = 0;
    float sum = 0.f;
    for (int i = tid; i < n; i += 256) {
        const float e = __expf(p[i] - m);
        ev[cnt++] = e;
        sum += e;
    }
    red[tid] = sum;
    __syncthreads();
    #pragma unroll
    for (int s = 128; s > 0; s >>= 1) {
        if (tid < s) red[tid] += red[tid + s];
        __syncthreads();
    }
    const float inv = 1.0f / red[0];

    cnt = 0;
    for (int i = tid; i < npad; i += 256) {
        const float v = (i < n) ? ev[cnt++] * inv : 0.0f;
        const bf16 b = __float2bfloat16_rn(v);
        Pb[off + i] = b;
        Ps[off + i] = __float2bfloat16_rn(v - __bfloat162float(b));
    }
}

// ---------------------------------------------------------------------------
extern "C" void kernel_launch(void* const* d_in, const int* in_sizes, int n_in,
                              void* d_out, int out_size)
{
    const float* hs = (const float*)d_in[0];
    // d_in[1] = attention_mask (causal; applied analytically)
    const float* W[4] = {(const float*)d_in[2], (const float*)d_in[3],
                         (const float*)d_in[4], (const float*)d_in[5]};
    float* out = (float*)d_out;

    bf16 *hb, *hs2, *wb, *ws, *qb, *qs, *kb, *ks2, *vtb, *vts, *pb, *ps, *aob, *aos;
    float* pp;
    cudaGetSymbolAddress((void**)&hb,  g_hb);
    cudaGetSymbolAddress((void**)&hs2, g_hs);
    cudaGetSymbolAddress((void**)&wb,  g_wb);
    cudaGetSymbolAddress((void**)&ws,  g_ws);
    cudaGetSymbolAddress((void**)&qb,  g_qb);
    cudaGetSymbolAddress((void**)&qs,  g_qs);
    cudaGetSymbolAddress((void**)&kb,  g_kb);
    cudaGetSymbolAddress((void**)&ks2, g_ks2);
    cudaGetSymbolAddress((void**)&vtb, g_vtb);
    cudaGetSymbolAddress((void**)&vts, g_vts);
    cudaGetSymbolAddress((void**)&pp,  g_p);
    cudaGetSymbolAddress((void**)&pb,  g_pb);
    cudaGetSymbolAddress((void**)&ps,  g_ps);
    cudaGetSymbolAddress((void**)&aob, g_aob);
    cudaGetSymbolAddress((void**)&aos, g_aos);

    cudaFuncSetAttribute(mm_k<0>, cudaFuncAttributeMaxDynamicSharedMemorySize, SMEM_DYN);
    cudaFuncSetAttribute(mm_k<1>, cudaFuncAttributeMaxDynamicSharedMemorySize, SMEM_DYN);
    cudaFuncSetAttribute(mm_k<2>, cudaFuncAttributeMaxDynamicSharedMemorySize, SMEM_DYN);
    cudaFuncSetAttribute(mm_k<3>, cudaFuncAttributeMaxDynamicSharedMemorySize, SMEM_DYN);
    cudaFuncSetAttribute(mm_k<4>, cudaFuncAttributeMaxDynamicSharedMemorySize, SMEM_DYN);

    const dim3 thr(256);
    const size_t WN = (size_t)kH * kH;

    // Pre-split inputs into bf16 planes
    split_k<<<(kM * kH / 4 + 255) / 256, thr>>>((const float4*)hs,
                                                (uint2*)hb, (uint2*)hs2, kM * kH / 4);
    for (int w = 0; w < 4; ++w)
        split_k<<<(kH * kH / 4 + 255) / 256, thr>>>((const float4*)W[w],
                                                    (uint2*)(wb + w * WN),
                                                    (uint2*)(ws + w * WN), kH * kH / 4);

    // Projections
    mm_k<0><<<dim3(kH / TN, kM / TM), thr, SMEM_DYN>>>(
        hb, hs2, wb + 0 * WN, ws + 0 * WN, nullptr, qb, qs, kH, kH, kH);
    mm_k<0><<<dim3(kH / TN, kM / TM), thr, SMEM_DYN>>>(
        hb, hs2, wb + 1 * WN, ws + 1 * WN, nullptr, kb, ks2, kH, kH, kH);
    mm_k<4><<<dim3(kH / TN, kM / TM), thr, SMEM_DYN>>>(
        hb, hs2, wb + 2 * WN, ws + 2 * WN, nullptr, vtb, vts, kH, kH, kH);

    // Scores (fp32, lower-tri blocks)
    mm_k<1><<<dim3(kS / TN, kS / TM, kB * kNH), thr, SMEM_DYN>>>(
        qb, qs, kb, ks2, pp, nullptr, nullptr, kHD, kHD, kHD);

    // Softmax -> split-bf16 probs
    softmax_k<<<kB * kNH * kS, 256>>>(pp, pb, ps);

    // PV (causal truncation) -> split planes
    mm_k<2><<<dim3(1, kS / TM, kB * kNH), thr, SMEM_DYN>>>(
        pb, ps, vtb, vts, nullptr, aob, aos, kS, kS, kS);

    // Output projection -> fp32
    mm_k<3><<<dim3(kH / TN, kM / TM), thr, SMEM_DYN>>>(
        aob, aos, wb + 3 * WN, ws + 3 * WN, out, nullptr, nullptr, kH, kH, kH);
}

// round 5
// speedup vs baseline: 5.3344x; 1.9117x over previous
#include <cuda_runtime.h>
#include <cuda_fp16.h>
#include <cstdint>
#include <cstddef>

using f16 = __half;

constexpr int kB  = 2;
constexpr int kS  = 2048;
constexpr int kH  = 2048;
constexpr int kNH = 16;
constexpr int kHD = 128;
constexpr int kM  = kB * kS;   // 4096

constexpr int TM = 128;
constexpr int TN = 128;
constexpr int KC = 64;                 // K elems per chunk (128B rows in smem)

constexpr int TILE   = 128 * 128;      // 16384 B per fp16 tile (128 rows x 128B)
constexpr int STAGE  = 2 * TILE;       // A, B
constexpr int NSTAGE = 3;
constexpr int SMEM_DYN = NSTAGE * STAGE;  // 98304 B

// ---- scratch: fp16 planes + fp32 scores ----
__device__ f16  g_hh [(size_t)kM * kH];
__device__ f16  g_wh [4][(size_t)kH * kH];            // q,k,v,o
__device__ f16  g_qh [(size_t)kB * kNH * kS * kHD];   // [b,h,s,d]
__device__ f16  g_kh [(size_t)kB * kNH * kS * kHD];   // [b,h,s,d]
__device__ f16  g_vth[(size_t)kB * kNH * kHD * kS];   // [b,h,d,s] (transposed)
__device__ float g_p [(size_t)kB * kNH * kS * kS];    // fp32 scores
__device__ f16  g_ph [(size_t)kB * kNH * kS * kS];    // fp16 probs
__device__ f16  g_aoh[(size_t)kM * kH];               // attn out [b*s, h*HD+d]

// ---------------------------------------------------------------------------
__device__ __forceinline__ uint32_t smem_u32(const void* p) {
    uint32_t a;
    asm("{ .reg .u64 t; cvta.to.shared.u64 t, %1; cvt.u32.u64 %0, t; }"
        : "=r"(a) : "l"(p));
    return a;
}
__device__ __forceinline__ void ldsm4(uint32_t* d, uint32_t addr) {
    asm volatile("ldmatrix.sync.aligned.m8n8.x4.shared.b16 {%0,%1,%2,%3}, [%4];"
                 : "=r"(d[0]), "=r"(d[1]), "=r"(d[2]), "=r"(d[3]) : "r"(addr));
}
__device__ __forceinline__ void mma_f16(float* c, const uint32_t* a,
                                        const uint32_t* b) {
    asm volatile(
        "mma.sync.aligned.m16n8k16.row.col.f32.f16.f16.f32 "
        "{%0,%1,%2,%3}, {%4,%5,%6,%7}, {%8,%9}, {%0,%1,%2,%3};"
        : "+f"(c[0]), "+f"(c[1]), "+f"(c[2]), "+f"(c[3])
        : "r"(a[0]), "r"(a[1]), "r"(a[2]), "r"(a[3]), "r"(b[0]), "r"(b[1]));
}
__device__ __forceinline__ void cpa16(uint32_t dst, const void* src) {
    asm volatile("cp.async.cg.shared.global [%0], [%1], 16;"
                 :: "r"(dst), "l"(__cvta_generic_to_global(src)));
}
#define CP_COMMIT() asm volatile("cp.async.commit_group;" ::: "memory")

__device__ __forceinline__ uint32_t pkh(f16 a, f16 b) {
    __half2 t(a, b);
    return *reinterpret_cast<uint32_t*>(&t);
}
__device__ __forceinline__ void store4h(f16* dst, float x, float y, float z, float w) {
    uint2 v = {pkh(__float2half_rn(x), __float2half_rn(y)),
               pkh(__float2half_rn(z), __float2half_rn(w))};
    *reinterpret_cast<uint2*>(dst) = v;
}

// ---------------------------------------------------------------------------
// fp32 -> fp16 plane, vectorized by 4.
__global__ void __launch_bounds__(256) split_k(const float4* __restrict__ src,
                                               uint2* __restrict__ dh, int n4)
{
    const int i = blockIdx.x * 256 + threadIdx.x;
    if (i >= n4) return;
    const float4 v = src[i];
    dh[i] = {pkh(__float2half_rn(v.x), __float2half_rn(v.y)),
             pkh(__float2half_rn(v.z), __float2half_rn(v.w))};
}

// ---------------------------------------------------------------------------
//  MODE 0: proj -> fp16 [b,h,s,d]            (Q, K)
//  MODE 4: proj -> fp16 [b,h,d,s]            (V transposed)
//  MODE 1: scores (lower-tri blocks) -> fp32 * HD^-0.5
//  MODE 2: PV (causal K truncation) -> fp16 [b*s, h*HD+d]
//  MODE 3: O proj -> fp32 row-major
// A is MxK K-major, B is NxK K-major, fp16.
// ---------------------------------------------------------------------------
template <int MODE>
__global__ void __launch_bounds__(256, 2)
mm_k(const f16* __restrict__ Ah, const f16* __restrict__ Bh,
     float* __restrict__ Cf, f16* __restrict__ Ch,
     int lda, int ldb, int Kd)
{
    extern __shared__ char dsm[];
    const int bx = blockIdx.x, by = blockIdx.y, bz = blockIdx.z;
    const int m0 = by * TM;
    const int n0 = bx * TN;

    if (MODE == 1 && n0 > m0) return;

    if (MODE == 1) {
        Ah += (size_t)bz * kS * kHD;
        Bh += (size_t)bz * kS * kHD;
        Cf += (size_t)bz * kS * kS;
    }
    if (MODE == 2) {
        Ah += (size_t)bz * kS * kS;
        Bh += (size_t)bz * kHD * kS;
    }
    const int kend = (MODE == 2) ? (m0 + TM) : Kd;
    const int NC   = kend / KC;

    const int tid  = threadIdx.x;
    const int lane = tid & 31;
    const int wid  = tid >> 5;
    const int wm   = (wid & 3) * 32;
    const int wn   = (wid >> 2) * 64;
    const uint32_t sb = smem_u32(dsm);

    float acc[2][8][4];
    #pragma unroll
    for (int i = 0; i < 2; ++i)
        #pragma unroll
        for (int j = 0; j < 8; ++j)
            #pragma unroll
            for (int t = 0; t < 4; ++t) acc[i][j][t] = 0.f;

    // swizzled 16B-chunk offset within a 128-row x 128B tile
    auto swz = [](int row, int chunk) -> uint32_t {
        return (uint32_t)(row * 128 + ((chunk ^ (row & 7)) << 4));
    };

    auto load_stage = [&](int c) {
        const uint32_t base = sb + (c % NSTAGE) * STAGE;
        const int k0 = c * KC;
        #pragma unroll
        for (int it = 0; it < 4; ++it) {
            const int idx = tid + it * 256;
            const int r = idx >> 3, ch = idx & 7;
            cpa16(base + swz(r, ch),        Ah + (size_t)(m0 + r) * lda + k0 + ch * 8);
            cpa16(base + TILE + swz(r, ch), Bh + (size_t)(n0 + r) * ldb + k0 + ch * 8);
        }
    };

    load_stage(0); CP_COMMIT();
    if (NC > 1) { load_stage(1); CP_COMMIT(); }
    else        { CP_COMMIT(); }   // keep group count consistent

    for (int c = 0; c < NC; ++c) {
        if (c + 2 <= NC) asm volatile("cp.async.wait_group 1;" ::: "memory");
        else             asm volatile("cp.async.wait_group 0;" ::: "memory");
        __syncthreads();

        const uint32_t ab = sb + (c % NSTAGE) * STAGE;
        const uint32_t bb = ab + TILE;
        #pragma unroll
        for (int ks = 0; ks < KC / 16; ++ks) {
            uint32_t af[2][4];
            #pragma unroll
            for (int i = 0; i < 2; ++i) {
                const int row = wm + 16 * i + (lane & 15);
                const int ch  = 2 * ks + (lane >> 4);
                ldsm4(af[i], ab + swz(row, ch));
            }
            #pragma unroll
            for (int jj = 0; jj < 4; ++jj) {
                const int row = wn + 16 * jj + (lane & 7) + ((lane >> 4) << 3);
                const int ch  = 2 * ks + ((lane >> 3) & 1);
                uint32_t bf[4];
                ldsm4(bf, bb + swz(row, ch));
                #pragma unroll
                for (int i = 0; i < 2; ++i)
                    #pragma unroll
                    for (int j2 = 0; j2 < 2; ++j2)
                        mma_f16(acc[i][2 * jj + j2], af[i], bf + 2 * j2);
            }
        }
        if (c + 2 < NC) { load_stage(c + 2); CP_COMMIT(); }
        __syncthreads();
    }

    // ---- epilogue: accumulators -> smem staging (fp32) -> gmem
    float* ep = reinterpret_cast<float*>(dsm);
    constexpr float scale = 0.088388347648318447f;  // 128^-0.5
    #pragma unroll
    for (int i = 0; i < 2; ++i)
        #pragma unroll
        for (int j = 0; j < 8; ++j) {
            const int r0 = wm + 16 * i + (lane >> 2);
            const int c0 = wn + 8 * j + 2 * (lane & 3);
            float v0 = acc[i][j][0], v1 = acc[i][j][1];
            float v2 = acc[i][j][2], v3 = acc[i][j][3];
            if (MODE == 1) { v0 *= scale; v1 *= scale; v2 *= scale; v3 *= scale; }
            ep[r0 * 132 + c0]           = v0;
            ep[r0 * 132 + c0 + 1]       = v1;
            ep[(r0 + 8) * 132 + c0]     = v2;
            ep[(r0 + 8) * 132 + c0 + 1] = v3;
        }
    __syncthreads();

    if (MODE == 4) {
        const int d    = tid >> 1;
        const int mseg = (tid & 1) * 64;
        const int h = n0 >> 7, b = m0 >> 11;
        const size_t base = ((size_t)((b * kNH + h) * kHD + d)) * kS +
                            (m0 & (kS - 1)) + mseg;
        #pragma unroll
        for (int j = 0; j < 16; ++j) {
            store4h(Ch + base + 4 * j,
                    ep[(mseg + 4 * j + 0) * 132 + d],
                    ep[(mseg + 4 * j + 1) * 132 + d],
                    ep[(mseg + 4 * j + 2) * 132 + d],
                    ep[(mseg + 4 * j + 3) * 132 + d]);
        }
    } else {
        const int r   = tid >> 1;
        const int c0  = (tid & 1) * 64;
        const int row = m0 + r;
        size_t base;
        if (MODE == 0) {
            const int b = row >> 11, s = row & (kS - 1), h = n0 >> 7;
            base = ((size_t)((b * kNH + h) * kS + s)) * kHD + c0;
        } else if (MODE == 1) {
            base = (size_t)row * kS + n0 + c0;
        } else if (MODE == 2) {
            const int b = bz >> 4, h = bz & 15;
            base = ((size_t)(b * kS + row)) * kH + h * kHD + c0;
        } else {
            base = (size_t)row * kH + n0 + c0;
        }
        #pragma unroll
        for (int j = 0; j < 16; ++j) {
            const int cc = c0 + 4 * j;
            const float v0 = ep[r * 132 + cc + 0];
            const float v1 = ep[r * 132 + cc + 1];
            const float v2 = ep[r * 132 + cc + 2];
            const float v3 = ep[r * 132 + cc + 3];
            if (MODE == 1 || MODE == 3) {
                float4 v = {v0, v1, v2, v3};
                *reinterpret_cast<float4*>(Cf + base + 4 * j) = v;
            } else {
                store4h(Ch + base + 4 * j, v0, v1, v2, v3);
            }
        }
    }
}

// ---------------------------------------------------------------------------
// Row-wise causal softmax: fp32 scores in, fp16 probabilities out.
// Zero-fills up to the 128-aligned boundary (PV truncates its K loop there).
// ---------------------------------------------------------------------------
__global__ void __launch_bounds__(256) softmax_k(const float* __restrict__ P,
                                                f16* __restrict__ Ph)
{
    const int r  = blockIdx.x;
    const int bh = r >> 11;
    const int q  = r & (kS - 1);
    const size_t off = (size_t)bh * kS * kS + (size_t)q * kS;
    const float* p = P + off;
    const int n    = q + 1;
    const int npad = ((q >> 7) + 1) << 7;

    const int tid = threadIdx.x;
    __shared__ float red[256];

    float m = -3.402823466e+38f;
    for (int i = tid; i < n; i += 256) m = fmaxf(m, p[i]);
    red[tid] = m;
    __syncthreads();
    #pragma unroll
    for (int s = 128; s > 0; s >>= 1) {
        if (tid < s) red[tid] = fmaxf(red[tid], red[tid + s]);
        __syncthreads();
    }
    m = red[0];
    __syncthreads();

    float ev[8];
    int cnt = 0;
    float sum = 0.f;
    for (int i = tid; i < n; i += 256) {
        const float e = __expf(p[i] - m);
        ev[cnt++] = e;
        sum += e;
    }
    red[tid] = sum;
    __syncthreads();
    #pragma unroll
    for (int s = 128; s > 0; s >>= 1) {
        if (tid < s) red[tid] += red[tid + s];
        __syncthreads();
    }
    const float inv = 1.0f / red[0];

    cnt = 0;
    for (int i = tid; i < npad; i += 256) {
        const float v = (i < n) ? ev[cnt++] * inv : 0.0f;
        Ph[off + i] = __float2half_rn(v);
    }
}

// ---------------------------------------------------------------------------
extern "C" void kernel_launch(void* const* d_in, const int* in_sizes, int n_in,
                              void* d_out, int out_size)
{
    const float* hs = (const float*)d_in[0];
    // d_in[1] = attention_mask (causal; applied analytically)
    const float* W[4] = {(const float*)d_in[2], (const float*)d_in[3],
                         (const float*)d_in[4], (const float*)d_in[5]};
    float* out = (float*)d_out;

    f16 *hh, *wh, *qh, *kh, *vth, *ph, *aoh;
    float* pp;
    cudaGetSymbolAddress((void**)&hh,  g_hh);
    cudaGetSymbolAddress((void**)&wh,  g_wh);
    cudaGetSymbolAddress((void**)&qh,  g_qh);
    cudaGetSymbolAddress((void**)&kh,  g_kh);
    cudaGetSymbolAddress((void**)&vth, g_vth);
    cudaGetSymbolAddress((void**)&pp,  g_p);
    cudaGetSymbolAddress((void**)&ph,  g_ph);
    cudaGetSymbolAddress((void**)&aoh, g_aoh);

    cudaFuncSetAttribute(mm_k<0>, cudaFuncAttributeMaxDynamicSharedMemorySize, SMEM_DYN);
    cudaFuncSetAttribute(mm_k<1>, cudaFuncAttributeMaxDynamicSharedMemorySize, SMEM_DYN);
    cudaFuncSetAttribute(mm_k<2>, cudaFuncAttributeMaxDynamicSharedMemorySize, SMEM_DYN);
    cudaFuncSetAttribute(mm_k<3>, cudaFuncAttributeMaxDynamicSharedMemorySize, SMEM_DYN);
    cudaFuncSetAttribute(mm_k<4>, cudaFuncAttributeMaxDynamicSharedMemorySize, SMEM_DYN);

    const dim3 thr(256);
    const size_t WN = (size_t)kH * kH;

    // fp32 -> fp16 conversion of inputs
    split_k<<<(kM * kH / 4 + 255) / 256, thr>>>((const float4*)hs, (uint2*)hh,
                                                kM * kH / 4);
    for (int w = 0; w < 4; ++w)
        split_k<<<(kH * kH / 4 + 255) / 256, thr>>>((const float4*)W[w],
                                                    (uint2*)(wh + w * WN),
                                                    kH * kH / 4);

    // Projections
    mm_k<0><<<dim3(kH / TN, kM / TM), thr, SMEM_DYN>>>(
        hh, wh + 0 * WN, nullptr, qh,  kH, kH, kH);
    mm_k<0><<<dim3(kH / TN, kM / TM), thr, SMEM_DYN>>>(
        hh, wh + 1 * WN, nullptr, kh,  kH, kH, kH);
    mm_k<4><<<dim3(kH / TN, kM / TM), thr, SMEM_DYN>>>(
        hh, wh + 2 * WN, nullptr, vth, kH, kH, kH);

    // Scores (fp32, lower-tri blocks)
    mm_k<1><<<dim3(kS / TN, kS / TM, kB * kNH), thr, SMEM_DYN>>>(
        qh, kh, pp, nullptr, kHD, kHD, kHD);

    // Softmax -> fp16 probs
    softmax_k<<<kB * kNH * kS, 256>>>(pp, ph);

    // PV (causal truncation) -> fp16
    mm_k<2><<<dim3(1, kS / TM, kB * kNH), thr, SMEM_DYN>>>(
        ph, vth, nullptr, aoh, kS, kS, kS);

    // Output projection -> fp32
    mm_k<3><<<dim3(kH / TN, kM / TM), thr, SMEM_DYN>>>(
        aoh, wh + 3 * WN, out, nullptr, kH, kH, kH);
}

// round 6
// speedup vs baseline: 8.2486x; 1.5463x over previous
#include <cuda_runtime.h>
#include <cuda_fp16.h>
#include <cstdint>
#include <cstddef>

using f16 = __half;

constexpr int kB  = 2;
constexpr int kS  = 2048;
constexpr int kH  = 2048;
constexpr int kNH = 16;
constexpr int kHD = 128;
constexpr int kM  = kB * kS;   // 4096

// ---------------- projection GEMM config (unchanged from R5) ----------------
constexpr int TM = 128;
constexpr int TN = 128;
constexpr int KC = 64;
constexpr int TILE   = 128 * 128;
constexpr int STAGE  = 2 * TILE;
constexpr int NSTAGE = 3;
constexpr int SMEM_DYN = NSTAGE * STAGE;  // 98304 B

// ---------------- fused attention config ----------------
constexpr int QT = 64;                    // q rows per CTA
constexpr int KT = 64;                    // kv rows per step
constexpr int ANS = 3;                    // stages
constexpr int AOFF_ST = 16384;            // after Q (16 KB)
constexpr int ASTAGE_B = 32768;           // K (16K) + V (16K)
constexpr int ATT_SMEM = AOFF_ST + ANS * ASTAGE_B;  // 114688 B

// ---- scratch ----
__device__ f16  g_hh [(size_t)kM * kH];
__device__ f16  g_wh [4][(size_t)kH * kH];            // q,k,v,o
__device__ f16  g_qh [(size_t)kB * kNH * kS * kHD];   // [b,h,s,d]
__device__ f16  g_kh [(size_t)kB * kNH * kS * kHD];   // [b,h,s,d]
__device__ f16  g_vth[(size_t)kB * kNH * kHD * kS];   // [b,h,d,s]
__device__ f16  g_aoh[(size_t)kM * kH];               // attn out [b*s, h*HD+d]

// ---------------------------------------------------------------------------
__device__ __forceinline__ uint32_t smem_u32(const void* p) {
    uint32_t a;
    asm("{ .reg .u64 t; cvta.to.shared.u64 t, %1; cvt.u32.u64 %0, t; }"
        : "=r"(a) : "l"(p));
    return a;
}
__device__ __forceinline__ void ldsm4(uint32_t* d, uint32_t addr) {
    asm volatile("ldmatrix.sync.aligned.m8n8.x4.shared.b16 {%0,%1,%2,%3}, [%4];"
                 : "=r"(d[0]), "=r"(d[1]), "=r"(d[2]), "=r"(d[3]) : "r"(addr));
}
__device__ __forceinline__ void mma_f16(float* c, const uint32_t* a,
                                        const uint32_t* b) {
    asm volatile(
        "mma.sync.aligned.m16n8k16.row.col.f32.f16.f16.f32 "
        "{%0,%1,%2,%3}, {%4,%5,%6,%7}, {%8,%9}, {%0,%1,%2,%3};"
        : "+f"(c[0]), "+f"(c[1]), "+f"(c[2]), "+f"(c[3])
        : "r"(a[0]), "r"(a[1]), "r"(a[2]), "r"(a[3]), "r"(b[0]), "r"(b[1]));
}
__device__ __forceinline__ void cpa16(uint32_t dst, const void* src) {
    asm volatile("cp.async.cg.shared.global [%0], [%1], 16;"
                 :: "r"(dst), "l"(__cvta_generic_to_global(src)));
}
#define CP_COMMIT() asm volatile("cp.async.commit_group;" ::: "memory")

__device__ __forceinline__ uint32_t pkh(f16 a, f16 b) {
    __half2 t(a, b);
    return *reinterpret_cast<uint32_t*>(&t);
}
__device__ __forceinline__ void store4h(f16* dst, float x, float y, float z, float w) {
    uint2 v = {pkh(__float2half_rn(x), __float2half_rn(y)),
               pkh(__float2half_rn(z), __float2half_rn(w))};
    *reinterpret_cast<uint2*>(dst) = v;
}
__device__ __forceinline__ float ex2f(float x) {
    float y;
    asm("ex2.approx.ftz.f32 %0, %1;" : "=f"(y) : "f"(x));
    return y;
}
__device__ __forceinline__ uint32_t swz(int row, int ch) {
    return (uint32_t)(row * 128 + ((ch ^ (row & 7)) << 4));
}

// ---------------------------------------------------------------------------
// fp32 -> fp16 plane, vectorized by 4.
__global__ void __launch_bounds__(256) split_k(const float4* __restrict__ src,
                                               uint2* __restrict__ dh, int n4)
{
    const int i = blockIdx.x * 256 + threadIdx.x;
    if (i >= n4) return;
    const float4 v = src[i];
    dh[i] = {pkh(__float2half_rn(v.x), __float2half_rn(v.y)),
             pkh(__float2half_rn(v.z), __float2half_rn(v.w))};
}

// ---------------------------------------------------------------------------
//  MODE 0: proj -> fp16 [b,h,s,d]   (Q, K)
//  MODE 4: proj -> fp16 [b,h,d,s]   (V transposed)
//  MODE 3: O proj -> fp32 row-major
// ---------------------------------------------------------------------------
template <int MODE>
__global__ void __launch_bounds__(256, 2)
mm_k(const f16* __restrict__ Ah, const f16* __restrict__ Bh,
     float* __restrict__ Cf, f16* __restrict__ Ch,
     int lda, int ldb, int Kd)
{
    extern __shared__ char dsm[];
    const int bx = blockIdx.x, by = blockIdx.y;
    const int m0 = by * TM;
    const int n0 = bx * TN;
    const int NC = Kd / KC;

    const int tid  = threadIdx.x;
    const int lane = tid & 31;
    const int wid  = tid >> 5;
    const int wm   = (wid & 3) * 32;
    const int wn   = (wid >> 2) * 64;
    const uint32_t sb = smem_u32(dsm);

    float acc[2][8][4];
    #pragma unroll
    for (int i = 0; i < 2; ++i)
        #pragma unroll
        for (int j = 0; j < 8; ++j)
            #pragma unroll
            for (int t = 0; t < 4; ++t) acc[i][j][t] = 0.f;

    auto load_stage = [&](int c) {
        const uint32_t base = sb + (c % NSTAGE) * STAGE;
        const int k0 = c * KC;
        #pragma unroll
        for (int it = 0; it < 4; ++it) {
            const int idx = tid + it * 256;
            const int r = idx >> 3, ch = idx & 7;
            cpa16(base + swz(r, ch),        Ah + (size_t)(m0 + r) * lda + k0 + ch * 8);
            cpa16(base + TILE + swz(r, ch), Bh + (size_t)(n0 + r) * ldb + k0 + ch * 8);
        }
    };

    load_stage(0); CP_COMMIT();
    if (NC > 1) load_stage(1);
    CP_COMMIT();

    for (int c = 0; c < NC; ++c) {
        if (c + 2 <= NC) asm volatile("cp.async.wait_group 1;" ::: "memory");
        else             asm volatile("cp.async.wait_group 0;" ::: "memory");
        __syncthreads();

        const uint32_t ab = sb + (c % NSTAGE) * STAGE;
        const uint32_t bb = ab + TILE;
        #pragma unroll
        for (int ks = 0; ks < KC / 16; ++ks) {
            uint32_t af[2][4];
            #pragma unroll
            for (int i = 0; i < 2; ++i) {
                const int row = wm + 16 * i + (lane & 15);
                const int ch  = 2 * ks + (lane >> 4);
                ldsm4(af[i], ab + swz(row, ch));
            }
            #pragma unroll
            for (int jj = 0; jj < 4; ++jj) {
                const int row = wn + 16 * jj + (lane & 7) + ((lane >> 4) << 3);
                const int ch  = 2 * ks + ((lane >> 3) & 1);
                uint32_t bf[4];
                ldsm4(bf, bb + swz(row, ch));
                #pragma unroll
                for (int i = 0; i < 2; ++i)
                    #pragma unroll
                    for (int j2 = 0; j2 < 2; ++j2)
                        mma_f16(acc[i][2 * jj + j2], af[i], bf + 2 * j2);
            }
        }
        if (c + 2 < NC) { load_stage(c + 2); CP_COMMIT(); }
        __syncthreads();
    }

    // ---- epilogue
    float* ep = reinterpret_cast<float*>(dsm);
    #pragma unroll
    for (int i = 0; i < 2; ++i)
        #pragma unroll
        for (int j = 0; j < 8; ++j) {
            const int r0 = wm + 16 * i + (lane >> 2);
            const int c0 = wn + 8 * j + 2 * (lane & 3);
            ep[r0 * 132 + c0]           = acc[i][j][0];
            ep[r0 * 132 + c0 + 1]       = acc[i][j][1];
            ep[(r0 + 8) * 132 + c0]     = acc[i][j][2];
            ep[(r0 + 8) * 132 + c0 + 1] = acc[i][j][3];
        }
    __syncthreads();

    if (MODE == 4) {
        const int d    = tid >> 1;
        const int mseg = (tid & 1) * 64;
        const int h = n0 >> 7, b = m0 >> 11;
        const size_t base = ((size_t)((b * kNH + h) * kHD + d)) * kS +
                            (m0 & (kS - 1)) + mseg;
        #pragma unroll
        for (int j = 0; j < 16; ++j) {
            store4h(Ch + base + 4 * j,
                    ep[(mseg + 4 * j + 0) * 132 + d],
                    ep[(mseg + 4 * j + 1) * 132 + d],
                    ep[(mseg + 4 * j + 2) * 132 + d],
                    ep[(mseg + 4 * j + 3) * 132 + d]);
        }
    } else {
        const int r   = tid >> 1;
        const int c0  = (tid & 1) * 64;
        const int row = m0 + r;
        size_t base;
        if (MODE == 0) {
            const int b = row >> 11, s = row & (kS - 1), h = n0 >> 7;
            base = ((size_t)((b * kNH + h) * kS + s)) * kHD + c0;
        } else {
            base = (size_t)row * kH + n0 + c0;
        }
        #pragma unroll
        for (int j = 0; j < 16; ++j) {
            const int cc = c0 + 4 * j;
            const float v0 = ep[r * 132 + cc + 0];
            const float v1 = ep[r * 132 + cc + 1];
            const float v2 = ep[r * 132 + cc + 2];
            const float v3 = ep[r * 132 + cc + 3];
            if (MODE == 3) {
                float4 v = {v0, v1, v2, v3};
                *reinterpret_cast<float4*>(Cf + base + 4 * j) = v;
            } else {
                store4h(Ch + base + 4 * j, v0, v1, v2, v3);
            }
        }
    }
}

// ---------------------------------------------------------------------------
// Fused flash attention: scores + online softmax + PV, causal.
// CTA = 4 warps, q-tile 64 (16 rows/warp), kv-step 64, 3-stage cp.async.
// Q,K read from [b,h,s,d]; V from transposed [b,h,d,s]; out fp16 [b*s, h*HD+d].
// ---------------------------------------------------------------------------
__global__ void __launch_bounds__(128, 2)
fattn_k(const f16* __restrict__ Qg, const f16* __restrict__ Kg,
        const f16* __restrict__ Vtg, f16* __restrict__ Og)
{
    extern __shared__ char dsm[];
    const int bh = blockIdx.y;
    const int qt = gridDim.x - 1 - blockIdx.x;   // longest CTAs first
    const int q0 = qt * QT;
    const int nsteps = qt + 1;
    const int b = bh >> 4, h = bh & 15;

    const f16* Qp = Qg  + (size_t)bh * kS * kHD;
    const f16* Kp = Kg  + (size_t)bh * kS * kHD;
    const f16* Vp = Vtg + (size_t)bh * kHD * kS;

    const int tid = threadIdx.x, lane = tid & 31, wid = tid >> 5;
    const int wr = wid * 16;                     // warp rows in q-tile
    const uint32_t sb = smem_u32(dsm);

    // prologue group 0: Q tile + stage 0
    #pragma unroll
    for (int it = 0; it < 8; ++it) {
        const int idx = tid + it * 128;
        const int r = idx >> 4, ch = idx & 15;
        cpa16(sb + ((ch >> 3) * 8192) + swz(r, ch & 7),
              Qp + (size_t)(q0 + r) * kHD + ch * 8);
    }
    auto load_stage = [&](int c) {
        const uint32_t base = sb + AOFF_ST + (c % ANS) * ASTAGE_B;
        const int kv0 = c * KT;
        #pragma unroll
        for (int it = 0; it < 8; ++it) {          // K: 64 rows x 128 d
            const int idx = tid + it * 128;
            const int r = idx >> 4, ch = idx & 15;
            cpa16(base + (ch >> 3) * 8192 + swz(r, ch & 7),
                  Kp + (size_t)(kv0 + r) * kHD + ch * 8);
        }
        #pragma unroll
        for (int it = 0; it < 8; ++it) {          // V: 128 d-rows x 64 kv
            const int idx = tid + it * 128;
            const int r = idx >> 3, ch = idx & 7;
            cpa16(base + 16384 + swz(r, ch),
                  Vp + (size_t)r * kS + kv0 + ch * 8);
        }
    };
    load_stage(0); CP_COMMIT();
    if (nsteps > 1) load_stage(1);
    CP_COMMIT();

    float oacc[16][4];
    #pragma unroll
    for (int n = 0; n < 16; ++n)
        #pragma unroll
        for (int t = 0; t < 4; ++t) oacc[n][t] = 0.f;
    float m0 = -1e30f, m1 = -1e30f, l0 = 0.f, l1 = 0.f;

    constexpr float CEXP = 0.12751791441801597f;  // 128^-0.5 * log2(e)

    for (int c = 0; c < nsteps; ++c) {
        if (c + 2 <= nsteps) asm volatile("cp.async.wait_group 1;" ::: "memory");
        else                 asm volatile("cp.async.wait_group 0;" ::: "memory");
        __syncthreads();

        const uint32_t kb = sb + AOFF_ST + (c % ANS) * ASTAGE_B;
        const uint32_t vb = kb + 16384;

        // ---- S = Q K^T (warp: 16 rows x 64 kv)
        float sacc[8][4];
        #pragma unroll
        for (int j = 0; j < 8; ++j)
            #pragma unroll
            for (int t = 0; t < 4; ++t) sacc[j][t] = 0.f;

        #pragma unroll
        for (int kc = 0; kc < 8; ++kc) {
            uint32_t af[4];
            {
                const int row = wr + (lane & 15);
                const int c16 = 2 * kc + (lane >> 4);
                ldsm4(af, sb + (c16 >> 3) * 8192 + swz(row, c16 & 7));
            }
            #pragma unroll
            for (int jj2 = 0; jj2 < 4; ++jj2) {
                const int row = 16 * jj2 + (lane & 7) + ((lane >> 4) << 3);
                const int c16 = 2 * kc + ((lane >> 3) & 1);
                uint32_t bf[4];
                ldsm4(bf, kb + (c16 >> 3) * 8192 + swz(row, c16 & 7));
                mma_f16(sacc[2 * jj2],     af, bf);
                mma_f16(sacc[2 * jj2 + 1], af, bf + 2);
            }
        }

        // ---- causal mask (diagonal step only; kv0 == q0 there)
        if (c == qt) {
            const int r0l = wr + (lane >> 2);
            const int r1l = r0l + 8;
            #pragma unroll
            for (int jj = 0; jj < 8; ++jj) {
                const int cb = 8 * jj + 2 * (lane & 3);
                if (cb     > r0l) sacc[jj][0] = -1e30f;
                if (cb + 1 > r0l) sacc[jj][1] = -1e30f;
                if (cb     > r1l) sacc[jj][2] = -1e30f;
                if (cb + 1 > r1l) sacc[jj][3] = -1e30f;
            }
        }

        // ---- online softmax
        float mx0 = -1e30f, mx1 = -1e30f;
        #pragma unroll
        for (int jj = 0; jj < 8; ++jj) {
            mx0 = fmaxf(mx0, fmaxf(sacc[jj][0], sacc[jj][1]));
            mx1 = fmaxf(mx1, fmaxf(sacc[jj][2], sacc[jj][3]));
        }
        mx0 = fmaxf(mx0, __shfl_xor_sync(0xFFFFFFFFu, mx0, 1));
        mx0 = fmaxf(mx0, __shfl_xor_sync(0xFFFFFFFFu, mx0, 2));
        mx1 = fmaxf(mx1, __shfl_xor_sync(0xFFFFFFFFu, mx1, 1));
        mx1 = fmaxf(mx1, __shfl_xor_sync(0xFFFFFFFFu, mx1, 2));

        const float mn0 = fmaxf(m0, mx0);
        const float mn1 = fmaxf(m1, mx1);
        const float a0 = ex2f((m0 - mn0) * CEXP);
        const float a1 = ex2f((m1 - mn1) * CEXP);
        m0 = mn0; m1 = mn1;

        float rs0 = 0.f, rs1 = 0.f;
        #pragma unroll
        for (int jj = 0; jj < 8; ++jj) {
            sacc[jj][0] = ex2f((sacc[jj][0] - m0) * CEXP);
            sacc[jj][1] = ex2f((sacc[jj][1] - m0) * CEXP);
            sacc[jj][2] = ex2f((sacc[jj][2] - m1) * CEXP);
            sacc[jj][3] = ex2f((sacc[jj][3] - m1) * CEXP);
            rs0 += sacc[jj][0] + sacc[jj][1];
            rs1 += sacc[jj][2] + sacc[jj][3];
        }
        rs0 += __shfl_xor_sync(0xFFFFFFFFu, rs0, 1);
        rs0 += __shfl_xor_sync(0xFFFFFFFFu, rs0, 2);
        rs1 += __shfl_xor_sync(0xFFFFFFFFu, rs1, 1);
        rs1 += __shfl_xor_sync(0xFFFFFFFFu, rs1, 2);
        l0 = l0 * a0 + rs0;
        l1 = l1 * a1 + rs1;

        #pragma unroll
        for (int n = 0; n < 16; ++n) {
            oacc[n][0] *= a0; oacc[n][1] *= a0;
            oacc[n][2] *= a1; oacc[n][3] *= a1;
        }

        // ---- O += P V  (P via C->A fragment identity)
        #pragma unroll
        for (int kc2 = 0; kc2 < 4; ++kc2) {
            uint32_t ap[4];
            ap[0] = pkh(__float2half_rn(sacc[2 * kc2][0]),
                        __float2half_rn(sacc[2 * kc2][1]));
            ap[1] = pkh(__float2half_rn(sacc[2 * kc2][2]),
                        __float2half_rn(sacc[2 * kc2][3]));
            ap[2] = pkh(__float2half_rn(sacc[2 * kc2 + 1][0]),
                        __float2half_rn(sacc[2 * kc2 + 1][1]));
            ap[3] = pkh(__float2half_rn(sacc[2 * kc2 + 1][2]),
                        __float2half_rn(sacc[2 * kc2 + 1][3]));
            #pragma unroll
            for (int nn2 = 0; nn2 < 8; ++nn2) {
                const int row = 16 * nn2 + (lane & 7) + ((lane >> 4) << 3);
                const int ch  = 2 * kc2 + ((lane >> 3) & 1);
                uint32_t bf[4];
                ldsm4(bf, vb + swz(row, ch));
                mma_f16(oacc[2 * nn2],     ap, bf);
                mma_f16(oacc[2 * nn2 + 1], ap, bf + 2);
            }
        }

        if (c + 2 < nsteps) { load_stage(c + 2); CP_COMMIT(); }
        __syncthreads();
    }

    // ---- normalize + store
    const float i0 = 1.f / l0;
    const float i1 = 1.f / l1;
    const int r0g = q0 + wr + (lane >> 2);
    f16* o0 = Og + (size_t)(b * kS + r0g) * kH + h * kHD;
    f16* o1 = Og + (size_t)(b * kS + r0g + 8) * kH + h * kHD;
    #pragma unroll
    for (int nb = 0; nb < 16; ++nb) {
        const int col = 8 * nb + 2 * (lane & 3);
        *reinterpret_cast<uint32_t*>(o0 + col) =
            pkh(__float2half_rn(oacc[nb][0] * i0),
                __float2half_rn(oacc[nb][1] * i0));
        *reinterpret_cast<uint32_t*>(o1 + col) =
            pkh(__float2half_rn(oacc[nb][2] * i1),
                __float2half_rn(oacc[nb][3] * i1));
    }
}

// ---------------------------------------------------------------------------
extern "C" void kernel_launch(void* const* d_in, const int* in_sizes, int n_in,
                              void* d_out, int out_size)
{
    const float* hs = (const float*)d_in[0];
    // d_in[1] = attention_mask (causal; applied analytically)
    const float* W[4] = {(const float*)d_in[2], (const float*)d_in[3],
                         (const float*)d_in[4], (const float*)d_in[5]};
    float* out = (float*)d_out;

    f16 *hh, *wh, *qh, *kh, *vth, *aoh;
    cudaGetSymbolAddress((void**)&hh,  g_hh);
    cudaGetSymbolAddress((void**)&wh,  g_wh);
    cudaGetSymbolAddress((void**)&qh,  g_qh);
    cudaGetSymbolAddress((void**)&kh,  g_kh);
    cudaGetSymbolAddress((void**)&vth, g_vth);
    cudaGetSymbolAddress((void**)&aoh, g_aoh);

    cudaFuncSetAttribute(mm_k<0>, cudaFuncAttributeMaxDynamicSharedMemorySize, SMEM_DYN);
    cudaFuncSetAttribute(mm_k<3>, cudaFuncAttributeMaxDynamicSharedMemorySize, SMEM_DYN);
    cudaFuncSetAttribute(mm_k<4>, cudaFuncAttributeMaxDynamicSharedMemorySize, SMEM_DYN);
    cudaFuncSetAttribute(fattn_k, cudaFuncAttributeMaxDynamicSharedMemorySize, ATT_SMEM);

    const dim3 thr(256);
    const size_t WN = (size_t)kH * kH;

    split_k<<<(kM * kH / 4 + 255) / 256, thr>>>((const float4*)hs, (uint2*)hh,
                                                kM * kH / 4);
    for (int w = 0; w < 4; ++w)
        split_k<<<(kH * kH / 4 + 255) / 256, thr>>>((const float4*)W[w],
                                                    (uint2*)(wh + w * WN),
                                                    kH * kH / 4);

    mm_k<0><<<dim3(kH / TN, kM / TM), thr, SMEM_DYN>>>(
        hh, wh + 0 * WN, nullptr, qh,  kH, kH, kH);
    mm_k<0><<<dim3(kH / TN, kM / TM), thr, SMEM_DYN>>>(
        hh, wh + 1 * WN, nullptr, kh,  kH, kH, kH);
    mm_k<4><<<dim3(kH / TN, kM / TM), thr, SMEM_DYN>>>(
        hh, wh + 2 * WN, nullptr, vth, kH, kH, kH);

    // fused scores + softmax + PV
    fattn_k<<<dim3(kS / QT, kB * kNH), 128, ATT_SMEM>>>(qh, kh, vth, aoh);

    mm_k<3><<<dim3(kH / TN, kM / TM), thr, SMEM_DYN>>>(
        aoh, wh + 3 * WN, out, nullptr, kH, kH, kH);
}

// round 7
// speedup vs baseline: 8.7017x; 1.0549x over previous
#include <cuda_runtime.h>
#include <cuda_fp16.h>
#include <cstdint>
#include <cstddef>

using f16 = __half;

constexpr int kB  = 2;
constexpr int kS  = 2048;
constexpr int kH  = 2048;
constexpr int kNH = 16;
constexpr int kHD = 128;
constexpr int kM  = kB * kS;   // 4096

// ---------------- projection GEMM config ----------------
constexpr int TM = 128;
constexpr int TN = 128;
constexpr int KC = 64;
constexpr int TILE   = 128 * 128;      // 16 KB per fp16 tile
constexpr int STAGE  = 2 * TILE;
constexpr int NSTAGE = 3;
constexpr int SMEM_DYN = NSTAGE * STAGE;  // 98304 B

// ---------------- fused attention config ----------------
constexpr int QT = 128;                   // q rows per CTA
constexpr int KT = 64;                    // kv rows per step
constexpr int ANS = 4;                    // stages
constexpr int AOFF_ST = 32768;            // after Q (32 KB)
constexpr int ASTAGE_B = 32768;           // K (16K) + V (16K)
constexpr int ATT_SMEM = AOFF_ST + ANS * ASTAGE_B;  // 163840 B

// ---- scratch ----
__device__ f16  g_hh [(size_t)kM * kH];
__device__ f16  g_wh [4][(size_t)kH * kH];            // q,k,v,o
__device__ f16  g_qh [(size_t)kB * kNH * kS * kHD];   // [b,h,s,d]
__device__ f16  g_kh [(size_t)kB * kNH * kS * kHD];   // [b,h,s,d]
__device__ f16  g_vth[(size_t)kB * kNH * kHD * kS];   // [b,h,d,s]
__device__ f16  g_aoh[(size_t)kM * kH];               // attn out [b*s, h*HD+d]

// ---------------------------------------------------------------------------
__device__ __forceinline__ uint32_t smem_u32(const void* p) {
    uint32_t a;
    asm("{ .reg .u64 t; cvta.to.shared.u64 t, %1; cvt.u32.u64 %0, t; }"
        : "=r"(a) : "l"(p));
    return a;
}
__device__ __forceinline__ void ldsm4(uint32_t* d, uint32_t addr) {
    asm volatile("ldmatrix.sync.aligned.m8n8.x4.shared.b16 {%0,%1,%2,%3}, [%4];"
                 : "=r"(d[0]), "=r"(d[1]), "=r"(d[2]), "=r"(d[3]) : "r"(addr));
}
__device__ __forceinline__ void mma_f16(float* c, const uint32_t* a,
                                        const uint32_t* b) {
    asm volatile(
        "mma.sync.aligned.m16n8k16.row.col.f32.f16.f16.f32 "
        "{%0,%1,%2,%3}, {%4,%5,%6,%7}, {%8,%9}, {%0,%1,%2,%3};"
        : "+f"(c[0]), "+f"(c[1]), "+f"(c[2]), "+f"(c[3])
        : "r"(a[0]), "r"(a[1]), "r"(a[2]), "r"(a[3]), "r"(b[0]), "r"(b[1]));
}
__device__ __forceinline__ void cpa16(uint32_t dst, const void* src) {
    asm volatile("cp.async.cg.shared.global [%0], [%1], 16;"
                 :: "r"(dst), "l"(__cvta_generic_to_global(src)));
}
#define CP_COMMIT() asm volatile("cp.async.commit_group;" ::: "memory")

__device__ __forceinline__ uint32_t pkh(f16 a, f16 b) {
    __half2 t(a, b);
    return *reinterpret_cast<uint32_t*>(&t);
}
__device__ __forceinline__ void store4h(f16* dst, float x, float y, float z, float w) {
    uint2 v = {pkh(__float2half_rn(x), __float2half_rn(y)),
               pkh(__float2half_rn(z), __float2half_rn(w))};
    *reinterpret_cast<uint2*>(dst) = v;
}
__device__ __forceinline__ float ex2f(float x) {
    float y;
    asm("ex2.approx.ftz.f32 %0, %1;" : "=f"(y) : "f"(x));
    return y;
}
__device__ __forceinline__ uint32_t swz(int row, int ch) {
    return (uint32_t)(row * 128 + ((ch ^ (row & 7)) << 4));
}

// ---------------------------------------------------------------------------
// fp32 -> fp16 plane, vectorized by 4.
__global__ void __launch_bounds__(256) split_k(const float4* __restrict__ src,
                                               uint2* __restrict__ dh, int n4)
{
    const int i = blockIdx.x * 256 + threadIdx.x;
    if (i >= n4) return;
    const float4 v = src[i];
    dh[i] = {pkh(__float2half_rn(v.x), __float2half_rn(v.y)),
             pkh(__float2half_rn(v.z), __float2half_rn(v.w))};
}

// ---------------------------------------------------------------------------
// Shared GEMM mainloop: computes acc[2][8][4] for a 128x128 tile.
// ---------------------------------------------------------------------------
__device__ __forceinline__ void gemm_core(const f16* __restrict__ Ah,
                                          const f16* __restrict__ Bh,
                                          int lda, int ldb, int m0, int n0,
                                          int NC, uint32_t sb, char* dsm,
                                          int tid, int lane, int wm, int wn,
                                          float acc[2][8][4])
{
    auto load_stage = [&](int c) {
        const uint32_t base = sb + (c % NSTAGE) * STAGE;
        const int k0 = c * KC;
        #pragma unroll
        for (int it = 0; it < 4; ++it) {
            const int idx = tid + it * 256;
            const int r = idx >> 3, ch = idx & 7;
            cpa16(base + swz(r, ch),        Ah + (size_t)(m0 + r) * lda + k0 + ch * 8);
            cpa16(base + TILE + swz(r, ch), Bh + (size_t)(n0 + r) * ldb + k0 + ch * 8);
        }
    };

    load_stage(0); CP_COMMIT();
    if (NC > 1) load_stage(1);
    CP_COMMIT();

    for (int c = 0; c < NC; ++c) {
        if (c + 2 <= NC) asm volatile("cp.async.wait_group 1;" ::: "memory");
        else             asm volatile("cp.async.wait_group 0;" ::: "memory");
        __syncthreads();

        const uint32_t ab = sb + (c % NSTAGE) * STAGE;
        const uint32_t bb = ab + TILE;
        #pragma unroll
        for (int ks = 0; ks < KC / 16; ++ks) {
            uint32_t af[2][4];
            #pragma unroll
            for (int i = 0; i < 2; ++i) {
                const int row = wm + 16 * i + (lane & 15);
                const int ch  = 2 * ks + (lane >> 4);
                ldsm4(af[i], ab + swz(row, ch));
            }
            #pragma unroll
            for (int jj = 0; jj < 4; ++jj) {
                const int row = wn + 16 * jj + (lane & 7) + ((lane >> 4) << 3);
                const int ch  = 2 * ks + ((lane >> 3) & 1);
                uint32_t bf[4];
                ldsm4(bf, bb + swz(row, ch));
                #pragma unroll
                for (int i = 0; i < 2; ++i)
                    #pragma unroll
                    for (int j2 = 0; j2 < 2; ++j2)
                        mma_f16(acc[i][2 * jj + j2], af[i], bf + 2 * j2);
            }
        }
        if (c + 2 < NC) { load_stage(c + 2); CP_COMMIT(); }
        __syncthreads();
    }
}

__device__ __forceinline__ void stage_acc(char* dsm, int lane, int wm, int wn,
                                          float acc[2][8][4])
{
    float* ep = reinterpret_cast<float*>(dsm);
    #pragma unroll
    for (int i = 0; i < 2; ++i)
        #pragma unroll
        for (int j = 0; j < 8; ++j) {
            const int r0 = wm + 16 * i + (lane >> 2);
            const int c0 = wn + 8 * j + 2 * (lane & 3);
            ep[r0 * 132 + c0]           = acc[i][j][0];
            ep[r0 * 132 + c0 + 1]       = acc[i][j][1];
            ep[(r0 + 8) * 132 + c0]     = acc[i][j][2];
            ep[(r0 + 8) * 132 + c0 + 1] = acc[i][j][3];
        }
}

// ---------------------------------------------------------------------------
// Fused QKV projection: grid.x = 48 (w = bx>>4, nb = bx&15).
//  w 0 -> Q [b,h,s,d], w 1 -> K [b,h,s,d], w 2 -> V transposed [b,h,d,s]
// ---------------------------------------------------------------------------
__global__ void __launch_bounds__(256, 2)
mm_qkv(const f16* __restrict__ hh, const f16* __restrict__ wh,
       f16* __restrict__ qh, f16* __restrict__ kh, f16* __restrict__ vth)
{
    extern __shared__ char dsm[];
    const int w  = blockIdx.x >> 4;
    const int nb = blockIdx.x & 15;
    const int m0 = blockIdx.y * TM;
    const int n0 = nb * TN;

    const int tid  = threadIdx.x;
    const int lane = tid & 31;
    const int wid  = tid >> 5;
    const int wm   = (wid & 3) * 32;
    const int wn   = (wid >> 2) * 64;
    const uint32_t sb = smem_u32(dsm);

    float acc[2][8][4];
    #pragma unroll
    for (int i = 0; i < 2; ++i)
        #pragma unroll
        for (int j = 0; j < 8; ++j)
            #pragma unroll
            for (int t = 0; t < 4; ++t) acc[i][j][t] = 0.f;

    const f16* Bh = wh + (size_t)w * kH * kH;
    gemm_core(hh, Bh, kH, kH, m0, n0, kH / KC, sb, dsm, tid, lane, wm, wn, acc);

    stage_acc(dsm, lane, wm, wn, acc);
    __syncthreads();

    float* ep = reinterpret_cast<float*>(dsm);
    if (w == 2) {
        // V transposed: [b,h,d,s]
        const int d    = tid >> 1;
        const int mseg = (tid & 1) * 64;
        const int h = nb, b = m0 >> 11;
        const size_t base = ((size_t)((b * kNH + h) * kHD + d)) * kS +
                            (m0 & (kS - 1)) + mseg;
        #pragma unroll
        for (int j = 0; j < 16; ++j) {
            store4h(vth + base + 4 * j,
                    ep[(mseg + 4 * j + 0) * 132 + d],
                    ep[(mseg + 4 * j + 1) * 132 + d],
                    ep[(mseg + 4 * j + 2) * 132 + d],
                    ep[(mseg + 4 * j + 3) * 132 + d]);
        }
    } else {
        f16* Ch = (w == 0) ? qh : kh;
        const int r   = tid >> 1;
        const int c0  = (tid & 1) * 64;
        const int row = m0 + r;
        const int b = row >> 11, s = row & (kS - 1), h = nb;
        const size_t base = ((size_t)((b * kNH + h) * kS + s)) * kHD + c0;
        #pragma unroll
        for (int j = 0; j < 16; ++j) {
            const int cc = 4 * j;
            store4h(Ch + base + cc,
                    ep[r * 132 + c0 + cc + 0], ep[r * 132 + c0 + cc + 1],
                    ep[r * 132 + c0 + cc + 2], ep[r * 132 + c0 + cc + 3]);
        }
    }
}

// ---------------------------------------------------------------------------
// Output projection: fp16 in -> fp32 out, row-major.
// ---------------------------------------------------------------------------
__global__ void __launch_bounds__(256, 2)
mm_o(const f16* __restrict__ Ah, const f16* __restrict__ Bh,
     float* __restrict__ Cf)
{
    extern __shared__ char dsm[];
    const int m0 = blockIdx.y * TM;
    const int n0 = blockIdx.x * TN;

    const int tid  = threadIdx.x;
    const int lane = tid & 31;
    const int wid  = tid >> 5;
    const int wm   = (wid & 3) * 32;
    const int wn   = (wid >> 2) * 64;
    const uint32_t sb = smem_u32(dsm);

    float acc[2][8][4];
    #pragma unroll
    for (int i = 0; i < 2; ++i)
        #pragma unroll
        for (int j = 0; j < 8; ++j)
            #pragma unroll
            for (int t = 0; t < 4; ++t) acc[i][j][t] = 0.f;

    gemm_core(Ah, Bh, kH, kH, m0, n0, kH / KC, sb, dsm, tid, lane, wm, wn, acc);

    stage_acc(dsm, lane, wm, wn, acc);
    __syncthreads();

    float* ep = reinterpret_cast<float*>(dsm);
    const int r  = tid >> 1;
    const int c0 = (tid & 1) * 64;
    const size_t base = (size_t)(m0 + r) * kH + n0 + c0;
    #pragma unroll
    for (int j = 0; j < 16; ++j) {
        const int cc = c0 + 4 * j;
        float4 v = {ep[r * 132 + cc + 0], ep[r * 132 + cc + 1],
                    ep[r * 132 + cc + 2], ep[r * 132 + cc + 3]};
        *reinterpret_cast<float4*>(Cf + base - c0 + cc) = v;
    }
}

// ---------------------------------------------------------------------------
// Fused flash attention, q-tile 128, kv-step 64, 4-stage / 3-ahead cp.async.
// 256 threads = 8 warps, each warp 16 q rows x 64 kv.
// ---------------------------------------------------------------------------
__global__ void __launch_bounds__(256, 1)
fattn_k(const f16* __restrict__ Qg, const f16* __restrict__ Kg,
        const f16* __restrict__ Vtg, f16* __restrict__ Og)
{
    extern __shared__ char dsm[];
    const int bh = blockIdx.y;
    const int qt = gridDim.x - 1 - blockIdx.x;   // longest CTAs first
    const int q0 = qt * QT;
    const int nsteps = 2 * (qt + 1);
    const int b = bh >> 4, h = bh & 15;

    const f16* Qp = Qg  + (size_t)bh * kS * kHD;
    const f16* Kp = Kg  + (size_t)bh * kS * kHD;
    const f16* Vp = Vtg + (size_t)bh * kHD * kS;

    const int tid = threadIdx.x, lane = tid & 31, wid = tid >> 5;
    const int wr = wid * 16;
    const uint32_t sb = smem_u32(dsm);

    // Q tile: 128 rows x 128 d, two 16 KB d-halves
    #pragma unroll
    for (int it = 0; it < 8; ++it) {
        const int idx = tid + it * 256;
        const int r = idx >> 4, ch = idx & 15;
        cpa16(sb + (ch >> 3) * 16384 + swz(r, ch & 7),
              Qp + (size_t)(q0 + r) * kHD + ch * 8);
    }
    auto load_stage = [&](int c) {
        const uint32_t base = sb + AOFF_ST + (c % ANS) * ASTAGE_B;
        const int kv0 = c * KT;
        #pragma unroll
        for (int it = 0; it < 4; ++it) {          // K: 64 rows x 128 d
            const int idx = tid + it * 256;
            const int r = idx >> 4, ch = idx & 15;
            cpa16(base + (ch >> 3) * 8192 + swz(r, ch & 7),
                  Kp + (size_t)(kv0 + r) * kHD + ch * 8);
        }
        #pragma unroll
        for (int it = 0; it < 4; ++it) {          // V: 128 d-rows x 64 kv
            const int idx = tid + it * 256;
            const int r = idx >> 3, ch = idx & 7;
            cpa16(base + 16384 + swz(r, ch),
                  Vp + (size_t)r * kS + kv0 + ch * 8);
        }
    };
    // prologue: 3 committed groups (empty commits keep the count aligned)
    load_stage(0); CP_COMMIT();
    if (nsteps > 1) load_stage(1);
    CP_COMMIT();
    if (nsteps > 2) load_stage(2);
    CP_COMMIT();

    float oacc[16][4];
    #pragma unroll
    for (int n = 0; n < 16; ++n)
        #pragma unroll
        for (int t = 0; t < 4; ++t) oacc[n][t] = 0.f;
    float m0 = -1e30f, m1 = -1e30f, l0 = 0.f, l1 = 0.f;

    constexpr float CEXP = 0.12751791441801597f;  // 128^-0.5 * log2(e)

    for (int c = 0; c < nsteps; ++c) {
        if      (nsteps - c > 2)  asm volatile("cp.async.wait_group 2;" ::: "memory");
        else if (nsteps - c == 2) asm volatile("cp.async.wait_group 1;" ::: "memory");
        else                      asm volatile("cp.async.wait_group 0;" ::: "memory");
        __syncthreads();

        const uint32_t kb = sb + AOFF_ST + (c % ANS) * ASTAGE_B;
        const uint32_t vb = kb + 16384;

        // ---- S = Q K^T
        float sacc[8][4];
        #pragma unroll
        for (int j = 0; j < 8; ++j)
            #pragma unroll
            for (int t = 0; t < 4; ++t) sacc[j][t] = 0.f;

        #pragma unroll
        for (int kc = 0; kc < 8; ++kc) {
            uint32_t af[4];
            {
                const int row = wr + (lane & 15);
                const int c16 = 2 * kc + (lane >> 4);
                ldsm4(af, sb + (c16 >> 3) * 16384 + swz(row, c16 & 7));
            }
            #pragma unroll
            for (int jj2 = 0; jj2 < 4; ++jj2) {
                const int row = 16 * jj2 + (lane & 7) + ((lane >> 4) << 3);
                const int c16 = 2 * kc + ((lane >> 3) & 1);
                uint32_t bf[4];
                ldsm4(bf, kb + (c16 >> 3) * 8192 + swz(row, c16 & 7));
                mma_f16(sacc[2 * jj2],     af, bf);
                mma_f16(sacc[2 * jj2 + 1], af, bf + 2);
            }
        }

        // ---- causal mask (only the last two steps can touch the diagonal)
        if (c >= nsteps - 2) {
            const int rel = c * KT - q0;
            const int r0l = wr + (lane >> 2);
            const int r1l = r0l + 8;
            #pragma unroll
            for (int jj = 0; jj < 8; ++jj) {
                const int cb = rel + 8 * jj + 2 * (lane & 3);
                if (cb     > r0l) sacc[jj][0] = -1e30f;
                if (cb + 1 > r0l) sacc[jj][1] = -1e30f;
                if (cb     > r1l) sacc[jj][2] = -1e30f;
                if (cb + 1 > r1l) sacc[jj][3] = -1e30f;
            }
        }

        // ---- online softmax
        float mx0 = -1e30f, mx1 = -1e30f;
        #pragma unroll
        for (int jj = 0; jj < 8; ++jj) {
            mx0 = fmaxf(mx0, fmaxf(sacc[jj][0], sacc[jj][1]));
            mx1 = fmaxf(mx1, fmaxf(sacc[jj][2], sacc[jj][3]));
        }
        mx0 = fmaxf(mx0, __shfl_xor_sync(0xFFFFFFFFu, mx0, 1));
        mx0 = fmaxf(mx0, __shfl_xor_sync(0xFFFFFFFFu, mx0, 2));
        mx1 = fmaxf(mx1, __shfl_xor_sync(0xFFFFFFFFu, mx1, 1));
        mx1 = fmaxf(mx1, __shfl_xor_sync(0xFFFFFFFFu, mx1, 2));

        const float mn0 = fmaxf(m0, mx0);
        const float mn1 = fmaxf(m1, mx1);
        const float a0 = ex2f((m0 - mn0) * CEXP);
        const float a1 = ex2f((m1 - mn1) * CEXP);
        m0 = mn0; m1 = mn1;

        float rs0 = 0.f, rs1 = 0.f;
        #pragma unroll
        for (int jj = 0; jj < 8; ++jj) {
            sacc[jj][0] = ex2f((sacc[jj][0] - m0) * CEXP);
            sacc[jj][1] = ex2f((sacc[jj][1] - m0) * CEXP);
            sacc[jj][2] = ex2f((sacc[jj][2] - m1) * CEXP);
            sacc[jj][3] = ex2f((sacc[jj][3] - m1) * CEXP);
            rs0 += sacc[jj][0] + sacc[jj][1];
            rs1 += sacc[jj][2] + sacc[jj][3];
        }
        rs0 += __shfl_xor_sync(0xFFFFFFFFu, rs0, 1);
        rs0 += __shfl_xor_sync(0xFFFFFFFFu, rs0, 2);
        rs1 += __shfl_xor_sync(0xFFFFFFFFu, rs1, 1);
        rs1 += __shfl_xor_sync(0xFFFFFFFFu, rs1, 2);
        l0 = l0 * a0 + rs0;
        l1 = l1 * a1 + rs1;

        #pragma unroll
        for (int n = 0; n < 16; ++n) {
            oacc[n][0] *= a0; oacc[n][1] *= a0;
            oacc[n][2] *= a1; oacc[n][3] *= a1;
        }

        // ---- O += P V
        #pragma unroll
        for (int kc2 = 0; kc2 < 4; ++kc2) {
            uint32_t ap[4];
            ap[0] = pkh(__float2half_rn(sacc[2 * kc2][0]),
                        __float2half_rn(sacc[2 * kc2][1]));
            ap[1] = pkh(__float2half_rn(sacc[2 * kc2][2]),
                        __float2half_rn(sacc[2 * kc2][3]));
            ap[2] = pkh(__float2half_rn(sacc[2 * kc2 + 1][0]),
                        __float2half_rn(sacc[2 * kc2 + 1][1]));
            ap[3] = pkh(__float2half_rn(sacc[2 * kc2 + 1][2]),
                        __float2half_rn(sacc[2 * kc2 + 1][3]));
            #pragma unroll
            for (int nn2 = 0; nn2 < 8; ++nn2) {
                const int row = 16 * nn2 + (lane & 7) + ((lane >> 4) << 3);
                const int ch  = 2 * kc2 + ((lane >> 3) & 1);
                uint32_t bf[4];
                ldsm4(bf, vb + swz(row, ch));
                mma_f16(oacc[2 * nn2],     ap, bf);
                mma_f16(oacc[2 * nn2 + 1], ap, bf + 2);
            }
        }

        if (c + 3 < nsteps) { load_stage(c + 3); CP_COMMIT(); }
        __syncthreads();
    }

    // ---- normalize + store
    const float i0 = 1.f / l0;
    const float i1 = 1.f / l1;
    const int r0g = q0 + wr + (lane >> 2);
    f16* o0 = Og + (size_t)(b * kS + r0g) * kH + h * kHD;
    f16* o1 = Og + (size_t)(b * kS + r0g + 8) * kH + h * kHD;
    #pragma unroll
    for (int nb = 0; nb < 16; ++nb) {
        const int col = 8 * nb + 2 * (lane & 3);
        *reinterpret_cast<uint32_t*>(o0 + col) =
            pkh(__float2half_rn(oacc[nb][0] * i0),
                __float2half_rn(oacc[nb][1] * i0));
        *reinterpret_cast<uint32_t*>(o1 + col) =
            pkh(__float2half_rn(oacc[nb][2] * i1),
                __float2half_rn(oacc[nb][3] * i1));
    }
}

// ---------------------------------------------------------------------------
extern "C" void kernel_launch(void* const* d_in, const int* in_sizes, int n_in,
                              void* d_out, int out_size)
{
    const float* hs = (const float*)d_in[0];
    // d_in[1] = attention_mask (causal; applied analytically)
    const float* W[4] = {(const float*)d_in[2], (const float*)d_in[3],
                         (const float*)d_in[4], (const float*)d_in[5]};
    float* out = (float*)d_out;

    f16 *hh, *wh, *qh, *kh, *vth, *aoh;
    cudaGetSymbolAddress((void**)&hh,  g_hh);
    cudaGetSymbolAddress((void**)&wh,  g_wh);
    cudaGetSymbolAddress((void**)&qh,  g_qh);
    cudaGetSymbolAddress((void**)&kh,  g_kh);
    cudaGetSymbolAddress((void**)&vth, g_vth);
    cudaGetSymbolAddress((void**)&aoh, g_aoh);

    cudaFuncSetAttribute(mm_qkv, cudaFuncAttributeMaxDynamicSharedMemorySize, SMEM_DYN);
    cudaFuncSetAttribute(mm_o,   cudaFuncAttributeMaxDynamicSharedMemorySize, SMEM_DYN);
    cudaFuncSetAttribute(fattn_k, cudaFuncAttributeMaxDynamicSharedMemorySize, ATT_SMEM);

    const dim3 thr(256);
    const size_t WN = (size_t)kH * kH;

    split_k<<<(kM * kH / 4 + 255) / 256, thr>>>((const float4*)hs, (uint2*)hh,
                                                kM * kH / 4);
    for (int w = 0; w < 4; ++w)
        split_k<<<(kH * kH / 4 + 255) / 256, thr>>>((const float4*)W[w],
                                                    (uint2*)(wh + w * WN),
                                                    kH * kH / 4);

    // Fused Q,K,V projections (one launch, 48 x 32 CTAs)
    mm_qkv<<<dim3(48, kM / TM), thr, SMEM_DYN>>>(hh, wh, qh, kh, vth);

    // Fused scores + softmax + PV
    fattn_k<<<dim3(kS / QT, kB * kNH), thr, ATT_SMEM>>>(qh, kh, vth, aoh);

    // Output projection
    mm_o<<<dim3(kH / TN, kM / TM), thr, SMEM_DYN>>>(aoh, wh + 3 * WN, out);
}

// round 8
// speedup vs baseline: 9.0198x; 1.0366x over previous
#include <cuda_runtime.h>
#include <cuda_fp16.h>
#include <cstdint>
#include <cstddef>

using f16 = __half;

constexpr int kB  = 2;
constexpr int kS  = 2048;
constexpr int kH  = 2048;
constexpr int kNH = 16;
constexpr int kHD = 128;
constexpr int kM  = kB * kS;   // 4096

// ---------------- projection GEMM config ----------------
constexpr int TM = 128;
constexpr int TN = 128;
constexpr int KC = 64;
constexpr int TILE   = 128 * 128;      // 16 KB per fp16 tile
constexpr int STAGE  = 2 * TILE;
constexpr int NSTAGE = 3;
constexpr int SMEM_DYN = NSTAGE * STAGE;  // 98304 B

// ---------------- fused attention config ----------------
constexpr int QT = 128;                   // q rows per CTA
constexpr int KT = 128;                   // kv rows per step
constexpr int ANS = 2;                    // double-buffered KV stages
constexpr int AOFF_ST = 32768;            // after Q (32 KB)
constexpr int ASTAGE_B = 65536;           // K (32K) + V (32K)
constexpr int ATT_SMEM = AOFF_ST + ANS * ASTAGE_B;  // 163840 B

// ---- scratch ----
__device__ f16  g_hh [(size_t)kM * kH];
__device__ f16  g_wh [4][(size_t)kH * kH];            // q,k,v,o
__device__ f16  g_qh [(size_t)kB * kNH * kS * kHD];   // [b,h,s,d]
__device__ f16  g_kh [(size_t)kB * kNH * kS * kHD];   // [b,h,s,d]
__device__ f16  g_vth[(size_t)kB * kNH * kHD * kS];   // [b,h,d,s]
__device__ f16  g_aoh[(size_t)kM * kH];               // attn out [b*s, h*HD+d]

// ---------------------------------------------------------------------------
__device__ __forceinline__ uint32_t smem_u32(const void* p) {
    uint32_t a;
    asm("{ .reg .u64 t; cvta.to.shared.u64 t, %1; cvt.u32.u64 %0, t; }"
        : "=r"(a) : "l"(p));
    return a;
}
__device__ __forceinline__ void ldsm4(uint32_t* d, uint32_t addr) {
    asm volatile("ldmatrix.sync.aligned.m8n8.x4.shared.b16 {%0,%1,%2,%3}, [%4];"
                 : "=r"(d[0]), "=r"(d[1]), "=r"(d[2]), "=r"(d[3]) : "r"(addr));
}
__device__ __forceinline__ void mma_f16(float* c, const uint32_t* a,
                                        const uint32_t* b) {
    asm volatile(
        "mma.sync.aligned.m16n8k16.row.col.f32.f16.f16.f32 "
        "{%0,%1,%2,%3}, {%4,%5,%6,%7}, {%8,%9}, {%0,%1,%2,%3};"
        : "+f"(c[0]), "+f"(c[1]), "+f"(c[2]), "+f"(c[3])
        : "r"(a[0]), "r"(a[1]), "r"(a[2]), "r"(a[3]), "r"(b[0]), "r"(b[1]));
}
__device__ __forceinline__ void cpa16(uint32_t dst, const void* src) {
    asm volatile("cp.async.cg.shared.global [%0], [%1], 16;"
                 :: "r"(dst), "l"(__cvta_generic_to_global(src)));
}
#define CP_COMMIT() asm volatile("cp.async.commit_group;" ::: "memory")

__device__ __forceinline__ uint32_t pkh(f16 a, f16 b) {
    __half2 t(a, b);
    return *reinterpret_cast<uint32_t*>(&t);
}
__device__ __forceinline__ void store4h(f16* dst, float x, float y, float z, float w) {
    uint2 v = {pkh(__float2half_rn(x), __float2half_rn(y)),
               pkh(__float2half_rn(z), __float2half_rn(w))};
    *reinterpret_cast<uint2*>(dst) = v;
}
__device__ __forceinline__ float ex2f(float x) {
    float y;
    asm("ex2.approx.ftz.f32 %0, %1;" : "=f"(y) : "f"(x));
    return y;
}
__device__ __forceinline__ uint32_t swz(int row, int ch) {
    return (uint32_t)(row * 128 + ((ch ^ (row & 7)) << 4));
}

// ---------------------------------------------------------------------------
// All fp32 -> fp16 conversions in ONE launch. Region by blockIdx
// (regions are multiples of the 256-thread block).
//   blocks [0, 8192)        : hidden (4096x2048)
//   blocks [8192 + w*4096..): weight w (2048x2048), w = 0..3
__global__ void __launch_bounds__(256)
split_all(const float4* __restrict__ hs,
          const float4* __restrict__ w0, const float4* __restrict__ w1,
          const float4* __restrict__ w2, const float4* __restrict__ w3,
          uint2* __restrict__ hh, uint2* __restrict__ wh)
{
    const int b = blockIdx.x;
    const float4* src;
    uint2* dst;
    int lb;
    if (b < 8192) { src = hs; dst = hh; lb = b; }
    else {
        const int w = (b - 8192) >> 12;
        lb = (b - 8192) & 4095;
        src = (w == 0) ? w0 : (w == 1) ? w1 : (w == 2) ? w2 : w3;
        dst = wh + (size_t)w * (kH * kH / 4);
    }
    const int i = lb * 256 + threadIdx.x;
    const float4 v = src[i];
    dst[i] = {pkh(__float2half_rn(v.x), __float2half_rn(v.y)),
              pkh(__float2half_rn(v.z), __float2half_rn(v.w))};
}

// ---------------------------------------------------------------------------
// Shared GEMM mainloop: computes acc[2][8][4] for a 128x128 tile.
// cp.async for chunk c+2 is issued BEFORE compute of chunk c (its target
// buffer was freed by the end-of-(c-1) barrier), maximizing LSU overlap.
// ---------------------------------------------------------------------------
__device__ __forceinline__ void gemm_core(const f16* __restrict__ Ah,
                                          const f16* __restrict__ Bh,
                                          int lda, int ldb, int m0, int n0,
                                          int NC, uint32_t sb, char* dsm,
                                          int tid, int lane, int wm, int wn,
                                          float acc[2][8][4])
{
    auto load_stage = [&](int c) {
        const uint32_t base = sb + (c % NSTAGE) * STAGE;
        const int k0 = c * KC;
        #pragma unroll
        for (int it = 0; it < 4; ++it) {
            const int idx = tid + it * 256;
            const int r = idx >> 3, ch = idx & 7;
            cpa16(base + swz(r, ch),        Ah + (size_t)(m0 + r) * lda + k0 + ch * 8);
            cpa16(base + TILE + swz(r, ch), Bh + (size_t)(n0 + r) * ldb + k0 + ch * 8);
        }
    };

    load_stage(0); CP_COMMIT();
    if (NC > 1) load_stage(1);
    CP_COMMIT();

    for (int c = 0; c < NC; ++c) {
        if (c + 2 <= NC) asm volatile("cp.async.wait_group 1;" ::: "memory");
        else             asm volatile("cp.async.wait_group 0;" ::: "memory");
        __syncthreads();

        if (c + 2 < NC) { load_stage(c + 2); CP_COMMIT(); }

        const uint32_t ab = sb + (c % NSTAGE) * STAGE;
        const uint32_t bb = ab + TILE;
        #pragma unroll
        for (int ks = 0; ks < KC / 16; ++ks) {
            uint32_t af[2][4];
            #pragma unroll
            for (int i = 0; i < 2; ++i) {
                const int row = wm + 16 * i + (lane & 15);
                const int ch  = 2 * ks + (lane >> 4);
                ldsm4(af[i], ab + swz(row, ch));
            }
            #pragma unroll
            for (int jj = 0; jj < 4; ++jj) {
                const int row = wn + 16 * jj + (lane & 7) + ((lane >> 4) << 3);
                const int ch  = 2 * ks + ((lane >> 3) & 1);
                uint32_t bf[4];
                ldsm4(bf, bb + swz(row, ch));
                #pragma unroll
                for (int i = 0; i < 2; ++i)
                    #pragma unroll
                    for (int j2 = 0; j2 < 2; ++j2)
                        mma_f16(acc[i][2 * jj + j2], af[i], bf + 2 * j2);
            }
        }
        __syncthreads();
    }
}

__device__ __forceinline__ void stage_acc(char* dsm, int lane, int wm, int wn,
                                          float acc[2][8][4])
{
    float* ep = reinterpret_cast<float*>(dsm);
    #pragma unroll
    for (int i = 0; i < 2; ++i)
        #pragma unroll
        for (int j = 0; j < 8; ++j) {
            const int r0 = wm + 16 * i + (lane >> 2);
            const int c0 = wn + 8 * j + 2 * (lane & 3);
            ep[r0 * 132 + c0]           = acc[i][j][0];
            ep[r0 * 132 + c0 + 1]       = acc[i][j][1];
            ep[(r0 + 8) * 132 + c0]     = acc[i][j][2];
            ep[(r0 + 8) * 132 + c0 + 1] = acc[i][j][3];
        }
}

// ---------------------------------------------------------------------------
// Fused QKV projection: grid.x = 48 (w = bx>>4, nb = bx&15).
// ---------------------------------------------------------------------------
__global__ void __launch_bounds__(256, 2)
mm_qkv(const f16* __restrict__ hh, const f16* __restrict__ wh,
       f16* __restrict__ qh, f16* __restrict__ kh, f16* __restrict__ vth)
{
    extern __shared__ char dsm[];
    const int w  = blockIdx.x >> 4;
    const int nb = blockIdx.x & 15;
    const int m0 = blockIdx.y * TM;
    const int n0 = nb * TN;

    const int tid  = threadIdx.x;
    const int lane = tid & 31;
    const int wid  = tid >> 5;
    const int wm   = (wid & 3) * 32;
    const int wn   = (wid >> 2) * 64;
    const uint32_t sb = smem_u32(dsm);

    float acc[2][8][4];
    #pragma unroll
    for (int i = 0; i < 2; ++i)
        #pragma unroll
        for (int j = 0; j < 8; ++j)
            #pragma unroll
            for (int t = 0; t < 4; ++t) acc[i][j][t] = 0.f;

    const f16* Bh = wh + (size_t)w * kH * kH;
    gemm_core(hh, Bh, kH, kH, m0, n0, kH / KC, sb, dsm, tid, lane, wm, wn, acc);

    stage_acc(dsm, lane, wm, wn, acc);
    __syncthreads();

    float* ep = reinterpret_cast<float*>(dsm);
    if (w == 2) {
        const int d    = tid >> 1;
        const int mseg = (tid & 1) * 64;
        const int h = nb, b = m0 >> 11;
        const size_t base = ((size_t)((b * kNH + h) * kHD + d)) * kS +
                            (m0 & (kS - 1)) + mseg;
        #pragma unroll
        for (int j = 0; j < 16; ++j) {
            store4h(vth + base + 4 * j,
                    ep[(mseg + 4 * j + 0) * 132 + d],
                    ep[(mseg + 4 * j + 1) * 132 + d],
                    ep[(mseg + 4 * j + 2) * 132 + d],
                    ep[(mseg + 4 * j + 3) * 132 + d]);
        }
    } else {
        f16* Ch = (w == 0) ? qh : kh;
        const int r   = tid >> 1;
        const int c0  = (tid & 1) * 64;
        const int row = m0 + r;
        const int b = row >> 11, s = row & (kS - 1), h = nb;
        const size_t base = ((size_t)((b * kNH + h) * kS + s)) * kHD + c0;
        #pragma unroll
        for (int j = 0; j < 16; ++j) {
            const int cc = 4 * j;
            store4h(Ch + base + cc,
                    ep[r * 132 + c0 + cc + 0], ep[r * 132 + c0 + cc + 1],
                    ep[r * 132 + c0 + cc + 2], ep[r * 132 + c0 + cc + 3]);
        }
    }
}

// ---------------------------------------------------------------------------
// Output projection: fp16 in -> fp32 out, row-major.
// ---------------------------------------------------------------------------
__global__ void __launch_bounds__(256, 2)
mm_o(const f16* __restrict__ Ah, const f16* __restrict__ Bh,
     float* __restrict__ Cf)
{
    extern __shared__ char dsm[];
    const int m0 = blockIdx.y * TM;
    const int n0 = blockIdx.x * TN;

    const int tid  = threadIdx.x;
    const int lane = tid & 31;
    const int wid  = tid >> 5;
    const int wm   = (wid & 3) * 32;
    const int wn   = (wid >> 2) * 64;
    const uint32_t sb = smem_u32(dsm);

    float acc[2][8][4];
    #pragma unroll
    for (int i = 0; i < 2; ++i)
        #pragma unroll
        for (int j = 0; j < 8; ++j)
            #pragma unroll
            for (int t = 0; t < 4; ++t) acc[i][j][t] = 0.f;

    gemm_core(Ah, Bh, kH, kH, m0, n0, kH / KC, sb, dsm, tid, lane, wm, wn, acc);

    stage_acc(dsm, lane, wm, wn, acc);
    __syncthreads();

    float* ep = reinterpret_cast<float*>(dsm);
    const int r  = tid >> 1;
    const int c0 = (tid & 1) * 64;
    const size_t base = (size_t)(m0 + r) * kH + n0;
    #pragma unroll
    for (int j = 0; j < 16; ++j) {
        const int cc = c0 + 4 * j;
        float4 v = {ep[r * 132 + cc + 0], ep[r * 132 + cc + 1],
                    ep[r * 132 + cc + 2], ep[r * 132 + cc + 3]};
        *reinterpret_cast<float4*>(Cf + base + cc) = v;
    }
}

// ---------------------------------------------------------------------------
// Fused flash attention, q-tile 128, kv-step 128, double-buffered cp.async.
// 256 threads = 8 warps, each warp 16 q rows x 128 kv.
// ---------------------------------------------------------------------------
__global__ void __launch_bounds__(256, 1)
fattn_k(const f16* __restrict__ Qg, const f16* __restrict__ Kg,
        const f16* __restrict__ Vtg, f16* __restrict__ Og)
{
    extern __shared__ char dsm[];
    const int bh = blockIdx.y;
    const int qt = gridDim.x - 1 - blockIdx.x;   // longest CTAs first
    const int q0 = qt * QT;
    const int nsteps = qt + 1;
    const int b = bh >> 4, h = bh & 15;

    const f16* Qp = Qg  + (size_t)bh * kS * kHD;
    const f16* Kp = Kg  + (size_t)bh * kS * kHD;
    const f16* Vp = Vtg + (size_t)bh * kHD * kS;

    const int tid = threadIdx.x, lane = tid & 31, wid = tid >> 5;
    const int wr = wid * 16;
    const uint32_t sb = smem_u32(dsm);

    // Q tile: 128 rows x 128 d, two 16 KB d-halves
    #pragma unroll
    for (int it = 0; it < 8; ++it) {
        const int idx = tid + it * 256;
        const int r = idx >> 4, ch = idx & 15;
        cpa16(sb + (ch >> 3) * 16384 + swz(r, ch & 7),
              Qp + (size_t)(q0 + r) * kHD + ch * 8);
    }
    auto load_stage = [&](int c) {
        const uint32_t base = sb + AOFF_ST + (c & 1) * ASTAGE_B;
        const int kv0 = c * KT;
        #pragma unroll
        for (int it = 0; it < 8; ++it) {          // K: 128 kv rows x 128 d
            const int idx = tid + it * 256;
            const int r = idx >> 4, ch = idx & 15;
            cpa16(base + (ch >> 3) * 16384 + swz(r, ch & 7),
                  Kp + (size_t)(kv0 + r) * kHD + ch * 8);
        }
        #pragma unroll
        for (int it = 0; it < 8; ++it) {          // V: 128 d rows x 128 kv
            const int idx = tid + it * 256;
            const int r = idx >> 4, ch = idx & 15;
            cpa16(base + 32768 + (ch >> 3) * 16384 + swz(r, ch & 7),
                  Vp + (size_t)r * kS + kv0 + ch * 8);
        }
    };
    load_stage(0); CP_COMMIT();

    float oacc[16][4];
    #pragma unroll
    for (int n = 0; n < 16; ++n)
        #pragma unroll
        for (int t = 0; t < 4; ++t) oacc[n][t] = 0.f;
    float m0 = -1e30f, m1 = -1e30f, l0 = 0.f, l1 = 0.f;

    constexpr float CEXP = 0.12751791441801597f;  // 128^-0.5 * log2(e)

    for (int c = 0; c < nsteps; ++c) {
        if (c + 1 < nsteps) {
            load_stage(c + 1); CP_COMMIT();
            asm volatile("cp.async.wait_group 1;" ::: "memory");
        } else {
            asm volatile("cp.async.wait_group 0;" ::: "memory");
        }
        __syncthreads();

        const uint32_t kb = sb + AOFF_ST + (c & 1) * ASTAGE_B;
        const uint32_t vb = kb + 32768;

        // ---- S = Q K^T  (warp: 16 q rows x 128 kv)
        float sacc[16][4];
        #pragma unroll
        for (int j = 0; j < 16; ++j)
            #pragma unroll
            for (int t = 0; t < 4; ++t) sacc[j][t] = 0.f;

        #pragma unroll
        for (int kc = 0; kc < 8; ++kc) {
            uint32_t af[4];
            {
                const int row = wr + (lane & 15);
                const int c16 = 2 * kc + (lane >> 4);
                ldsm4(af, sb + (c16 >> 3) * 16384 + swz(row, c16 & 7));
            }
            #pragma unroll
            for (int jj2 = 0; jj2 < 8; ++jj2) {
                const int row = 16 * jj2 + (lane & 7) + ((lane >> 4) << 3);
                const int c16 = 2 * kc + ((lane >> 3) & 1);
                uint32_t bf[4];
                ldsm4(bf, kb + (c16 >> 3) * 16384 + swz(row, c16 & 7));
                mma_f16(sacc[2 * jj2],     af, bf);
                mma_f16(sacc[2 * jj2 + 1], af, bf + 2);
            }
        }

        // ---- causal mask (diagonal step only)
        if (c == nsteps - 1) {
            const int r0l = wr + (lane >> 2);
            const int r1l = r0l + 8;
            #pragma unroll
            for (int jj = 0; jj < 16; ++jj) {
                const int cb = 8 * jj + 2 * (lane & 3);
                if (cb     > r0l) sacc[jj][0] = -1e30f;
                if (cb + 1 > r0l) sacc[jj][1] = -1e30f;
                if (cb     > r1l) sacc[jj][2] = -1e30f;
                if (cb + 1 > r1l) sacc[jj][3] = -1e30f;
            }
        }

        // ---- online softmax
        float mx0 = -1e30f, mx1 = -1e30f;
        #pragma unroll
        for (int jj = 0; jj < 16; ++jj) {
            mx0 = fmaxf(mx0, fmaxf(sacc[jj][0], sacc[jj][1]));
            mx1 = fmaxf(mx1, fmaxf(sacc[jj][2], sacc[jj][3]));
        }
        mx0 = fmaxf(mx0, __shfl_xor_sync(0xFFFFFFFFu, mx0, 1));
        mx0 = fmaxf(mx0, __shfl_xor_sync(0xFFFFFFFFu, mx0, 2));
        mx1 = fmaxf(mx1, __shfl_xor_sync(0xFFFFFFFFu, mx1, 1));
        mx1 = fmaxf(mx1, __shfl_xor_sync(0xFFFFFFFFu, mx1, 2));

        const float mn0 = fmaxf(m0, mx0);
        const float mn1 = fmaxf(m1, mx1);
        const float a0 = ex2f((m0 - mn0) * CEXP);
        const float a1 = ex2f((m1 - mn1) * CEXP);
        m0 = mn0; m1 = mn1;

        float rs0 = 0.f, rs1 = 0.f;
        #pragma unroll
        for (int jj = 0; jj < 16; ++jj) {
            sacc[jj][0] = ex2f((sacc[jj][0] - m0) * CEXP);
            sacc[jj][1] = ex2f((sacc[jj][1] - m0) * CEXP);
            sacc[jj][2] = ex2f((sacc[jj][2] - m1) * CEXP);
            sacc[jj][3] = ex2f((sacc[jj][3] - m1) * CEXP);
            rs0 += sacc[jj][0] + sacc[jj][1];
            rs1 += sacc[jj][2] + sacc[jj][3];
        }
        rs0 += __shfl_xor_sync(0xFFFFFFFFu, rs0, 1);
        rs0 += __shfl_xor_sync(0xFFFFFFFFu, rs0, 2);
        rs1 += __shfl_xor_sync(0xFFFFFFFFu, rs1, 1);
        rs1 += __shfl_xor_sync(0xFFFFFFFFu, rs1, 2);
        l0 = l0 * a0 + rs0;
        l1 = l1 * a1 + rs1;

        #pragma unroll
        for (int n = 0; n < 16; ++n) {
            oacc[n][0] *= a0; oacc[n][1] *= a0;
            oacc[n][2] *= a1; oacc[n][3] *= a1;
        }

        // ---- O += P V
        #pragma unroll
        for (int kc2 = 0; kc2 < 8; ++kc2) {
            uint32_t ap[4];
            ap[0] = pkh(__float2half_rn(sacc[2 * kc2][0]),
                        __float2half_rn(sacc[2 * kc2][1]));
            ap[1] = pkh(__float2half_rn(sacc[2 * kc2][2]),
                        __float2half_rn(sacc[2 * kc2][3]));
            ap[2] = pkh(__float2half_rn(sacc[2 * kc2 + 1][0]),
                        __float2half_rn(sacc[2 * kc2 + 1][1]));
            ap[3] = pkh(__float2half_rn(sacc[2 * kc2 + 1][2]),
                        __float2half_rn(sacc[2 * kc2 + 1][3]));
            #pragma unroll
            for (int nn2 = 0; nn2 < 8; ++nn2) {
                const int row = 16 * nn2 + (lane & 7) + ((lane >> 4) << 3);
                const int c16 = 2 * kc2 + ((lane >> 3) & 1);
                uint32_t bf[4];
                ldsm4(bf, vb + (c16 >> 3) * 16384 + swz(row, c16 & 7));
                mma_f16(oacc[2 * nn2],     ap, bf);
                mma_f16(oacc[2 * nn2 + 1], ap, bf + 2);
            }
        }
        __syncthreads();
    }

    // ---- normalize + store
    const float i0 = 1.f / l0;
    const float i1 = 1.f / l1;
    const int r0g = q0 + wr + (lane >> 2);
    f16* o0 = Og + (size_t)(b * kS + r0g) * kH + h * kHD;
    f16* o1 = Og + (size_t)(b * kS + r0g + 8) * kH + h * kHD;
    #pragma unroll
    for (int nb = 0; nb < 16; ++nb) {
        const int col = 8 * nb + 2 * (lane & 3);
        *reinterpret_cast<uint32_t*>(o0 + col) =
            pkh(__float2half_rn(oacc[nb][0] * i0),
                __float2half_rn(oacc[nb][1] * i0));
        *reinterpret_cast<uint32_t*>(o1 + col) =
            pkh(__float2half_rn(oacc[nb][2] * i1),
                __float2half_rn(oacc[nb][3] * i1));
    }
}

// ---------------------------------------------------------------------------
extern "C" void kernel_launch(void* const* d_in, const int* in_sizes, int n_in,
                              void* d_out, int out_size)
{
    const float* hs = (const float*)d_in[0];
    // d_in[1] = attention_mask (causal; applied analytically)
    const float* W[4] = {(const float*)d_in[2], (const float*)d_in[3],
                         (const float*)d_in[4], (const float*)d_in[5]};
    float* out = (float*)d_out;

    f16 *hh, *wh, *qh, *kh, *vth, *aoh;
    cudaGetSymbolAddress((void**)&hh,  g_hh);
    cudaGetSymbolAddress((void**)&wh,  g_wh);
    cudaGetSymbolAddress((void**)&qh,  g_qh);
    cudaGetSymbolAddress((void**)&kh,  g_kh);
    cudaGetSymbolAddress((void**)&vth, g_vth);
    cudaGetSymbolAddress((void**)&aoh, g_aoh);

    cudaFuncSetAttribute(mm_qkv, cudaFuncAttributeMaxDynamicSharedMemorySize, SMEM_DYN);
    cudaFuncSetAttribute(mm_o,   cudaFuncAttributeMaxDynamicSharedMemorySize, SMEM_DYN);
    cudaFuncSetAttribute(fattn_k, cudaFuncAttributeMaxDynamicSharedMemorySize, ATT_SMEM);

    const dim3 thr(256);
    const size_t WN = (size_t)kH * kH;

    // All fp32 -> fp16 conversions, one launch (24576 blocks)
    split_all<<<8192 + 4 * 4096, thr>>>((const float4*)hs,
                                        (const float4*)W[0], (const float4*)W[1],
                                        (const float4*)W[2], (const float4*)W[3],
                                        (uint2*)hh, (uint2*)wh);

    // Fused Q,K,V projections
    mm_qkv<<<dim3(48, kM / TM), thr, SMEM_DYN>>>(hh, wh, qh, kh, vth);

    // Fused scores + softmax + PV
    fattn_k<<<dim3(kS / QT, kB * kNH), thr, ATT_SMEM>>>(qh, kh, vth, aoh);

    // Output projection
    mm_o<<<dim3(kH / TN, kM / TM), thr, SMEM_DYN>>>(aoh, wh + 3 * WN, out);
}